// round 15
// baseline (speedup 1.0000x reference)
#include <cuda_runtime.h>
#include <cuda_bf16.h>
#include <math.h>
#include <stdint.h>

#define NN 50000
#define NE 600000
#define DD 128
#define NBLK_E ((NE + 127) / 128)   // 4688
#define NBLK_N ((NN + 127) / 128)   // 391

// ---------------- device scratch ----------------
__device__ __align__(16) float g_nodeABDE[NN * 512];   // [Ax|Bx|Dx|Ex]
__device__ __align__(16) float g_eij[(size_t)NE * DD];
__device__ __align__(16) float g_num[NN * DD];
__device__ __align__(16) float g_den[NN * DD];
__device__ __align__(16) float g_t[NN * DD];
__device__ __align__(16) float g_x1[NN * DD];
__device__ __align__(16) float g_x2[NN * DD];
__device__ __align__(16) float g_mid[NN * 256];
// [0]=e_sum [128]=e_sq [256]=x_sum [384]=x_sq [512]=n1_sum [640]=n1_sq [768]=n2_sum [896]=n2_sq
__device__ float g_stats[8 * DD];
// pre-split weights (transposed, [n][k] bf16 hi/lo)
__device__ __align__(16) __nv_bfloat16 g_wct_hi[128 * 128];
__device__ __align__(16) __nv_bfloat16 g_wct_lo[128 * 128];
__device__ __align__(16) __nv_bfloat16 g_w4t_hi[4 * 128 * 128];
__device__ __align__(16) __nv_bfloat16 g_w4t_lo[4 * 128 * 128];
__device__ __align__(16) __nv_bfloat16 g_wf1t_hi[256 * 128];
__device__ __align__(16) __nv_bfloat16 g_wf1t_lo[256 * 128];
__device__ __align__(16) __nv_bfloat16 g_wf2t_hi[128 * 256];
__device__ __align__(16) __nv_bfloat16 g_wf2t_lo[128 * 256];
__device__ float g_bias4[512];
__device__ float g_biasf[384];   // [0:256)=bf1, [256:384)=bf2

static __device__ __forceinline__ float4 ld4(const float* p) {
    return *reinterpret_cast<const float4*>(p);
}
static __device__ __forceinline__ float4 ldcs4(const float* p) {
    return __ldcs(reinterpret_cast<const float4*>(p));
}
static __device__ __forceinline__ void st4(float* p, float4 v) {
    *reinterpret_cast<float4*>(p) = v;
}
static __device__ __forceinline__ void stcs4(float* p, float4 v) {
    __stcs(reinterpret_cast<float4*>(p), v);
}
static __device__ __forceinline__ void pf_l2(const void* p) {
    asm volatile("prefetch.global.L2 [%0];" :: "l"(p));
}
static __device__ __forceinline__ uint32_t smem_u32(const void* p) {
    uint32_t a;
    asm("{ .reg .u64 t; cvta.to.shared.u64 t, %1; cvt.u32.u64 %0, t; }" : "=r"(a) : "l"(p));
    return a;
}
static __device__ __forceinline__ void ldsm_x4(uint32_t* r, uint32_t addr) {
    asm volatile("ldmatrix.sync.aligned.m8n8.x4.shared.b16 {%0,%1,%2,%3}, [%4];"
                 : "=r"(r[0]), "=r"(r[1]), "=r"(r[2]), "=r"(r[3]) : "r"(addr));
}
static __device__ __forceinline__ void mma_bf16(float* d, const uint32_t* a, const uint32_t* b) {
    asm volatile("mma.sync.aligned.m16n8k16.row.col.f32.bf16.bf16.f32 "
                 "{%0,%1,%2,%3}, {%4,%5,%6,%7}, {%8,%9}, {%0,%1,%2,%3};"
                 : "+f"(d[0]), "+f"(d[1]), "+f"(d[2]), "+f"(d[3])
                 : "r"(a[0]), "r"(a[1]), "r"(a[2]), "r"(a[3]), "r"(b[0]), "r"(b[1]));
}
static __device__ __forceinline__ void split_store(char* hi, char* lo, float4 v) {
    __nv_bfloat16 h0 = __float2bfloat16(v.x);
    __nv_bfloat16 h1 = __float2bfloat16(v.y);
    __nv_bfloat16 h2 = __float2bfloat16(v.z);
    __nv_bfloat16 h3 = __float2bfloat16(v.w);
    __nv_bfloat16 l0 = __float2bfloat16(v.x - __bfloat162float(h0));
    __nv_bfloat16 l1 = __float2bfloat16(v.y - __bfloat162float(h1));
    __nv_bfloat16 l2 = __float2bfloat16(v.z - __bfloat162float(h2));
    __nv_bfloat16 l3 = __float2bfloat16(v.w - __bfloat162float(h3));
    *reinterpret_cast<__nv_bfloat162*>(hi)     = __nv_bfloat162(h0, h1);
    *reinterpret_cast<__nv_bfloat162*>(hi + 4) = __nv_bfloat162(h2, h3);
    *reinterpret_cast<__nv_bfloat162*>(lo)     = __nv_bfloat162(l0, l1);
    *reinterpret_cast<__nv_bfloat162*>(lo + 4) = __nv_bfloat162(l2, l3);
}

// smem layout for gemm kernels: K-split halves, 64 bf16 cols + 8 pad = 144B pitch
#define EP2      144
#define OFF_AHI  0
#define OFF_ALO  18432
#define OFF_BHI  36864
#define OFF_BLO  55296
#define SM_GEMM_TOTAL 73728
#define SM_FFN_TOTAL  74752   // + scs/shs (2*128 f32)

// ===== K0a: WC -> WC^T bf16 hi/lo ==========================================
__global__ void k_prep_wct(const float* __restrict__ WC)
{
    int idx = blockIdx.x * 256 + threadIdx.x;     // 16384
    int n = idx >> 7, k = idx & 127;
    float w = WC[k * 128 + n];
    __nv_bfloat16 h = __float2bfloat16(w);
    g_wct_hi[n * 128 + k] = h;
    g_wct_lo[n * 128 + k] = __float2bfloat16(w - __bfloat162float(h));
}

// ===== K0b: [WA|WB|WD|WE]^T -> bf16 hi/lo + bias pack ======================
__global__ void k_prep_w4(
    const float* __restrict__ WA, const float* __restrict__ WB,
    const float* __restrict__ WD, const float* __restrict__ WE,
    const float* __restrict__ bA, const float* __restrict__ bB,
    const float* __restrict__ bD, const float* __restrict__ bE)
{
    int idx = blockIdx.x * 256 + threadIdx.x;     // 65536
    int mat = idx >> 14, rem = idx & 16383;
    int n = rem >> 7, k = rem & 127;
    const float* W = (mat == 0) ? WA : (mat == 1) ? WB : (mat == 2) ? WD : WE;
    float w = W[k * 128 + n];
    __nv_bfloat16 h = __float2bfloat16(w);
    g_w4t_hi[idx] = h;
    g_w4t_lo[idx] = __float2bfloat16(w - __bfloat162float(h));
    if (k == 0) {
        const float* b = (mat == 0) ? bA : (mat == 1) ? bB : (mat == 2) ? bD : bE;
        g_bias4[mat * 128 + n] = b[n];
    }
}

// ===== K0c: Wf1^T, Wf2^T -> bf16 hi/lo + bias pack =========================
__global__ void k_prep_wf(
    const float* __restrict__ Wf1, const float* __restrict__ Wf2,
    const float* __restrict__ bf1, const float* __restrict__ bf2)
{
    int idx = blockIdx.x * 256 + threadIdx.x;     // 65536
    if (idx < 32768) {
        int n = idx >> 7, k = idx & 127;
        float w = Wf1[k * 256 + n];
        __nv_bfloat16 h = __float2bfloat16(w);
        g_wf1t_hi[n * 128 + k] = h;
        g_wf1t_lo[n * 128 + k] = __float2bfloat16(w - __bfloat162float(h));
        if (k == 0) g_biasf[n] = bf1[n];
    } else {
        int rem = idx - 32768;
        int n = rem >> 8, k = rem & 255;
        float w = Wf2[k * 128 + n];
        __nv_bfloat16 h = __float2bfloat16(w);
        g_wf2t_hi[n * 256 + k] = h;
        g_wf2t_lo[n * 256 + k] = __float2bfloat16(w - __bfloat162float(h));
        if (k == 0) g_biasf[256 + n] = bf2[n];
    }
}

// ===== K1: node 4-GEMM via mma.sync bf16 split =============================
__global__ __launch_bounds__(512, 2) void k_node_gemm_mma(const float* __restrict__ x)
{
    extern __shared__ char smc[];
    const uint32_t smb = smem_u32(smc);
    const int tid = threadIdx.x;
    const int wid = tid >> 5, lid = tid & 31;
    const int eb = blockIdx.x * 128;
    const int mat = blockIdx.y;
    const int slab = (wid >> 1) * 16;
    const int colhalf = (wid & 1) * 64;

    float acc[8][4];
#pragma unroll
    for (int i = 0; i < 8; i++)
#pragma unroll
        for (int j = 0; j < 4; j++) acc[i][j] = 0.f;

    const uint32_t aBase = smb + OFF_AHI + (slab + (lid & 15)) * EP2 + (lid >> 4) * 16;
    const uint32_t bRowSel = (lid & 7) + ((lid >> 4) << 3);
    const uint32_t bColSel = ((lid >> 3) & 1) * 16;

#pragma unroll 1
    for (int ks = 0; ks < 2; ks++) {
        if (ks) __syncthreads();
        {
            const float4 z4 = make_float4(0.f, 0.f, 0.f, 0.f);
            for (int t = tid; t < 2048; t += 512) {
                int r = t >> 4, c4 = t & 15, k0 = c4 * 4;
                float4 v = (eb + r < NN) ? ld4(x + (size_t)(eb + r) * 128 + ks * 64 + k0) : z4;
                split_store(smc + OFF_AHI + r * EP2 + k0 * 2,
                            smc + OFF_ALO + r * EP2 + k0 * 2, v);
            }
        }
        {
            const uint32_t* bh = reinterpret_cast<const uint32_t*>(g_w4t_hi) + mat * 8192;
            const uint32_t* bl = reinterpret_cast<const uint32_t*>(g_w4t_lo) + mat * 8192;
            for (int t = tid; t < 4096; t += 512) {
                int n = t >> 5, k2 = t & 31;
                *reinterpret_cast<uint32_t*>(smc + OFF_BHI + n * EP2 + k2 * 4) = bh[n * 64 + ks * 32 + k2];
                *reinterpret_cast<uint32_t*>(smc + OFF_BLO + n * EP2 + k2 * 4) = bl[n * 64 + ks * 32 + k2];
            }
        }
        __syncthreads();

#pragma unroll
        for (int kk = 0; kk < 4; kk++) {
            uint32_t aH[4], aL[4];
            uint32_t aaddr = aBase + kk * 32;
            ldsm_x4(aH, aaddr);
            ldsm_x4(aL, aaddr + (OFF_ALO - OFF_AHI));
#pragma unroll
            for (int ntp = 0; ntp < 4; ntp++) {
                uint32_t bH[4], bL[4];
                uint32_t baddr = smb + OFF_BHI + (colhalf + ntp * 16 + bRowSel) * EP2
                               + kk * 32 + bColSel;
                ldsm_x4(bH, baddr);
                ldsm_x4(bL, baddr + (OFF_BLO - OFF_BHI));
                mma_bf16(acc[2 * ntp],     aH, &bH[0]);
                mma_bf16(acc[2 * ntp],     aH, &bL[0]);
                mma_bf16(acc[2 * ntp],     aL, &bH[0]);
                mma_bf16(acc[2 * ntp + 1], aH, &bH[2]);
                mma_bf16(acc[2 * ntp + 1], aH, &bL[2]);
                mma_bf16(acc[2 * ntp + 1], aL, &bH[2]);
            }
        }
    }

    {
        int r0 = slab + (lid >> 2);
        int cb2 = (lid & 3) * 2;
        bool ok0 = (eb + r0 < NN), ok1 = (eb + r0 + 8 < NN);
        float* d0 = g_nodeABDE + (size_t)(eb + r0) * 512 + mat * 128 + colhalf;
        float* d1 = g_nodeABDE + (size_t)(eb + r0 + 8) * 512 + mat * 128 + colhalf;
        const float* bp = g_bias4 + mat * 128 + colhalf;
#pragma unroll
        for (int nt = 0; nt < 8; nt++) {
            int c = nt * 8 + cb2;
            float b0 = bp[c], b1 = bp[c + 1];
            if (ok0) *reinterpret_cast<float2*>(d0 + c) = make_float2(acc[nt][0] + b0, acc[nt][1] + b1);
            if (ok1) *reinterpret_cast<float2*>(d1 + c) = make_float2(acc[nt][2] + b0, acc[nt][3] + b1);
        }
    }
}

// ===== K2: FUSED edge GEMM + epilogue; L2-prefetch of gather rows ==========
__global__ __launch_bounds__(512, 2) void k_edge_fused(
    const float* __restrict__ e, const int* __restrict__ eidx,
    const float* __restrict__ bC)
{
    extern __shared__ char smc[];
    const uint32_t smb = smem_u32(smc);
    const int tid = threadIdx.x;
    const int wid = tid >> 5, lid = tid & 31;
    const int eb = blockIdx.x * 128;
    const int slab = (wid >> 1) * 16;
    const int colhalf = (wid & 1) * 64;

    // ---- warm L2 with the epilogue's gather rows; overlaps the GEMM phase ----
    if (tid < 384) {
        int li = tid / 3, kind = tid - li * 3;
        int eg = eb + li;
        if (eg < NE) {
            const char* base;
            if (kind == 0)      base = (const char*)(g_nodeABDE + (size_t)eidx[NE + eg] * 512 + 256); // Dx[dst]
            else if (kind == 1) base = (const char*)(g_nodeABDE + (size_t)eidx[eg] * 512 + 384);      // Ex[src]
            else                base = (const char*)(g_nodeABDE + (size_t)eidx[eg] * 512 + 128);      // Bx[src]
            pf_l2(base); pf_l2(base + 128); pf_l2(base + 256); pf_l2(base + 384);
        }
    }

    float acc[8][4];
#pragma unroll
    for (int i = 0; i < 8; i++)
#pragma unroll
        for (int j = 0; j < 4; j++) acc[i][j] = 0.f;

    const uint32_t aBase = smb + OFF_AHI + (slab + (lid & 15)) * EP2 + (lid >> 4) * 16;
    const uint32_t bRowSel = (lid & 7) + ((lid >> 4) << 3);
    const uint32_t bColSel = ((lid >> 3) & 1) * 16;

#pragma unroll 1
    for (int ks = 0; ks < 2; ks++) {
        if (ks) __syncthreads();
        {
            const float4 z4 = make_float4(0.f, 0.f, 0.f, 0.f);
            for (int t = tid; t < 2048; t += 512) {
                int r = t >> 4, c4 = t & 15, k0 = c4 * 4;
                float4 v = (eb + r < NE) ? ldcs4(e + (size_t)(eb + r) * 128 + ks * 64 + k0) : z4;
                split_store(smc + OFF_AHI + r * EP2 + k0 * 2,
                            smc + OFF_ALO + r * EP2 + k0 * 2, v);
            }
        }
        {
            const uint32_t* bh = reinterpret_cast<const uint32_t*>(g_wct_hi);
            const uint32_t* bl = reinterpret_cast<const uint32_t*>(g_wct_lo);
            for (int t = tid; t < 4096; t += 512) {
                int n = t >> 5, k2 = t & 31;
                *reinterpret_cast<uint32_t*>(smc + OFF_BHI + n * EP2 + k2 * 4) = bh[n * 64 + ks * 32 + k2];
                *reinterpret_cast<uint32_t*>(smc + OFF_BLO + n * EP2 + k2 * 4) = bl[n * 64 + ks * 32 + k2];
            }
        }
        __syncthreads();

#pragma unroll
        for (int kk = 0; kk < 4; kk++) {
            uint32_t aH[4], aL[4];
            uint32_t aaddr = aBase + kk * 32;
            ldsm_x4(aH, aaddr);
            ldsm_x4(aL, aaddr + (OFF_ALO - OFF_AHI));
#pragma unroll
            for (int ntp = 0; ntp < 4; ntp++) {
                uint32_t bH[4], bL[4];
                uint32_t baddr = smb + OFF_BHI + (colhalf + ntp * 16 + bRowSel) * EP2
                               + kk * 32 + bColSel;
                ldsm_x4(bH, baddr);
                ldsm_x4(bL, baddr + (OFF_BLO - OFF_BHI));
                mma_bf16(acc[2 * ntp],     aH, &bH[0]);
                mma_bf16(acc[2 * ntp],     aH, &bL[0]);
                mma_bf16(acc[2 * ntp],     aL, &bH[0]);
                mma_bf16(acc[2 * ntp + 1], aH, &bH[2]);
                mma_bf16(acc[2 * ntp + 1], aH, &bL[2]);
                mma_bf16(acc[2 * ntp + 1], aL, &bH[2]);
            }
        }
    }
    __syncthreads();   // mainloop done reading A/B smem

    // ---- stage Ce into smem (pitch 130 f32) ----
    float* Dsm = reinterpret_cast<float*>(smc);
    {
        int r0 = slab + (lid >> 2);
        int cb2 = (lid & 3) * 2;
#pragma unroll
        for (int nt = 0; nt < 8; nt++) {
            int c = colhalf + nt * 8 + cb2;
            *reinterpret_cast<float2*>(&Dsm[r0 * 130 + c])       = make_float2(acc[nt][0], acc[nt][1]);
            *reinterpret_cast<float2*>(&Dsm[(r0 + 8) * 130 + c]) = make_float2(acc[nt][2], acc[nt][3]);
        }
    }
    __syncthreads();

    // ---- epilogue ----
    const int tx = tid & 15, ty = tid >> 4;
    float4 bc0 = ld4(bC + tx * 4), bc1 = ld4(bC + 64 + tx * 4);
    float ssum[8], ssq[8];
#pragma unroll
    for (int j = 0; j < 8; j++) { ssum[j] = 0.f; ssq[j] = 0.f; }

    const float4* nb = reinterpret_cast<const float4*>(g_nodeABDE);
    float4* numb = reinterpret_cast<float4*>(g_num);
    float4* denb = reinterpret_cast<float4*>(g_den);

#pragma unroll
    for (int i = 0; i < 4; i++) {
        int lr = ty * 4 + i;
        int eg = eb + lr;
        if (eg >= NE) continue;
        int src = eidx[eg];
        int dst = eidx[NE + eg];
#pragma unroll
        for (int cc = 0; cc < 2; cc++) {
            int c4 = tx + cc * 16;
            int col = c4 * 4;
            float a0 = Dsm[lr * 130 + col + 0];
            float a1 = Dsm[lr * 130 + col + 1];
            float a2 = Dsm[lr * 130 + col + 2];
            float a3 = Dsm[lr * 130 + col + 3];
            float4 dx = nb[(size_t)dst * 128 + 64 + c4];
            float4 ex = nb[(size_t)src * 128 + 96 + c4];
            float4 bx = nb[(size_t)src * 128 + 32 + c4];
            float4 bc = cc ? bc1 : bc0;
            float4 eij;
            eij.x = a0 + bc.x + dx.x + ex.x;
            eij.y = a1 + bc.y + dx.y + ex.y;
            eij.z = a2 + bc.z + dx.z + ex.z;
            eij.w = a3 + bc.w + dx.w + ex.w;
            stcs4(g_eij + (size_t)eg * 128 + col, eij);
            float4 sg;
            sg.x = 1.f / (1.f + __expf(-eij.x));
            sg.y = 1.f / (1.f + __expf(-eij.y));
            sg.z = 1.f / (1.f + __expf(-eij.z));
            sg.w = 1.f / (1.f + __expf(-eij.w));
            atomicAdd(numb + (size_t)dst * 32 + c4,
                      make_float4(sg.x * bx.x, sg.y * bx.y, sg.z * bx.z, sg.w * bx.w));
            atomicAdd(denb + (size_t)dst * 32 + c4, sg);
            ssum[cc * 4 + 0] += eij.x; ssq[cc * 4 + 0] += eij.x * eij.x;
            ssum[cc * 4 + 1] += eij.y; ssq[cc * 4 + 1] += eij.y * eij.y;
            ssum[cc * 4 + 2] += eij.z; ssq[cc * 4 + 2] += eij.z * eij.z;
            ssum[cc * 4 + 3] += eij.w; ssq[cc * 4 + 3] += eij.w * eij.w;
        }
    }
    __syncthreads();   // Dsm dead; reuse for stats reduce

    float* redS = reinterpret_cast<float*>(smc);            // 32 x 128
    float* redQ = reinterpret_cast<float*>(smc) + 4096;     // 32 x 128
#pragma unroll
    for (int cc = 0; cc < 2; cc++)
#pragma unroll
        for (int j = 0; j < 4; j++) {
            redS[ty * 128 + cc * 64 + tx * 4 + j] = ssum[cc * 4 + j];
            redQ[ty * 128 + cc * 64 + tx * 4 + j] = ssq[cc * 4 + j];
        }
    __syncthreads();
    if (tid < 128) {
        float s = 0.f, q = 0.f;
#pragma unroll
        for (int t = 0; t < 32; t++) { s += redS[t * 128 + tid]; q += redQ[t * 128 + tid]; }
        atomicAdd(&g_stats[tid], s);
        atomicAdd(&g_stats[128 + tid], q);
    }
}

// ===== K3: t = Ax + num/(den+eps); x-stats =================================
__global__ __launch_bounds__(256) void k_node_t2()
{
    __shared__ float sS[8 * 128], sQ[8 * 128];
    const int tid = threadIdx.x;
    const int c4 = tid & 31, g = tid >> 5;
    const int rb = blockIdx.x * 64;
    float s[4] = {0, 0, 0, 0}, q[4] = {0, 0, 0, 0};
#pragma unroll
    for (int p = 0; p < 8; p++) {
        int r = rb + p * 8 + g;
        if (r < NN) {
            float4 ax = ld4(g_nodeABDE + (size_t)r * 512 + c4 * 4);
            float4 nu = ld4(g_num + (size_t)r * 128 + c4 * 4);
            float4 de = ld4(g_den + (size_t)r * 128 + c4 * 4);
            float4 t;
            t.x = ax.x + nu.x / (de.x + 1e-6f);
            t.y = ax.y + nu.y / (de.y + 1e-6f);
            t.z = ax.z + nu.z / (de.z + 1e-6f);
            t.w = ax.w + nu.w / (de.w + 1e-6f);
            st4(g_t + (size_t)r * 128 + c4 * 4, t);
            s[0] += t.x; q[0] += t.x * t.x;
            s[1] += t.y; q[1] += t.y * t.y;
            s[2] += t.z; q[2] += t.z * t.z;
            s[3] += t.w; q[3] += t.w * t.w;
        }
    }
#pragma unroll
    for (int j = 0; j < 4; j++) { sS[g * 128 + c4 * 4 + j] = s[j]; sQ[g * 128 + c4 * 4 + j] = q[j]; }
    __syncthreads();
    if (tid < 128) {
        float a = 0.f, b = 0.f;
#pragma unroll
        for (int t = 0; t < 8; t++) { a += sS[t * 128 + tid]; b += sQ[t * 128 + tid]; }
        atomicAdd(&g_stats[256 + tid], a);
        atomicAdd(&g_stats[384 + tid], b);
    }
}

// ===== K4: x1 = x + relu(BN_x(t)); n1-stats ================================
__global__ __launch_bounds__(256) void k_node_x12(
    const float* __restrict__ x,
    const float* __restrict__ gx, const float* __restrict__ bex)
{
    __shared__ float sS[8 * 128], sQ[8 * 128];
    const int tid = threadIdx.x;
    const int c4 = tid & 31, g = tid >> 5;
    const int rb = blockIdx.x * 64;
    float sc[4], sh[4];
#pragma unroll
    for (int j = 0; j < 4; j++) {
        int c = c4 * 4 + j;
        float m = g_stats[256 + c] * (1.f / NN);
        float v = g_stats[384 + c] * (1.f / NN) - m * m;
        sc[j] = gx[c] * rsqrtf(v + 1e-5f);
        sh[j] = bex[c] - m * sc[j];
    }
    float s[4] = {0, 0, 0, 0}, q[4] = {0, 0, 0, 0};
#pragma unroll
    for (int p = 0; p < 8; p++) {
        int r = rb + p * 8 + g;
        if (r < NN) {
            float4 t = ld4(g_t + (size_t)r * 128 + c4 * 4);
            float4 xv = ld4(x + (size_t)r * 128 + c4 * 4);
            float4 o;
            o.x = xv.x + fmaxf(t.x * sc[0] + sh[0], 0.f);
            o.y = xv.y + fmaxf(t.y * sc[1] + sh[1], 0.f);
            o.z = xv.z + fmaxf(t.z * sc[2] + sh[2], 0.f);
            o.w = xv.w + fmaxf(t.w * sc[3] + sh[3], 0.f);
            st4(g_x1 + (size_t)r * 128 + c4 * 4, o);
            s[0] += o.x; q[0] += o.x * o.x;
            s[1] += o.y; q[1] += o.y * o.y;
            s[2] += o.z; q[2] += o.z * o.z;
            s[3] += o.w; q[3] += o.w * o.w;
        }
    }
#pragma unroll
    for (int j = 0; j < 4; j++) { sS[g * 128 + c4 * 4 + j] = s[j]; sQ[g * 128 + c4 * 4 + j] = q[j]; }
    __syncthreads();
    if (tid < 128) {
        float a = 0.f, b = 0.f;
#pragma unroll
        for (int t = 0; t < 8; t++) { a += sS[t * 128 + tid]; b += sQ[t * 128 + tid]; }
        atomicAdd(&g_stats[512 + tid], a);
        atomicAdd(&g_stats[640 + tid], b);
    }
}

// ===== K5a: FFN GEMM1: mid = relu(BN_n1(x1) @ Wf1 + bf1) ===================
__global__ __launch_bounds__(512, 2) void k_ffn1(
    const float* __restrict__ gn1, const float* __restrict__ ben1)
{
    extern __shared__ char smc[];
    const uint32_t smb = smem_u32(smc);
    float* scs = reinterpret_cast<float*>(smc + SM_GEMM_TOTAL);
    float* shs = scs + 128;
    const int tid = threadIdx.x;
    const int wid = tid >> 5, lid = tid & 31;
    const int eb = blockIdx.x * 128;
    const int colsec = blockIdx.y;
    const int slab = (wid >> 1) * 16;
    const int colhalf = (wid & 1) * 64;

    if (tid < 128) {
        float m = g_stats[512 + tid] * (1.f / NN);
        float v = g_stats[640 + tid] * (1.f / NN) - m * m;
        float sc = gn1[tid] * rsqrtf(v + 1e-5f);
        scs[tid] = sc;
        shs[tid] = ben1[tid] - m * sc;
    }
    __syncthreads();

    float acc[8][4];
#pragma unroll
    for (int i = 0; i < 8; i++)
#pragma unroll
        for (int j = 0; j < 4; j++) acc[i][j] = 0.f;

    const uint32_t aBase = smb + OFF_AHI + (slab + (lid & 15)) * EP2 + (lid >> 4) * 16;
    const uint32_t bRowSel = (lid & 7) + ((lid >> 4) << 3);
    const uint32_t bColSel = ((lid >> 3) & 1) * 16;

#pragma unroll 1
    for (int ks = 0; ks < 2; ks++) {
        if (ks) __syncthreads();
        {
            const float4 z4 = make_float4(0.f, 0.f, 0.f, 0.f);
            for (int t = tid; t < 2048; t += 512) {
                int r = t >> 4, c4 = t & 15, k0 = c4 * 4;
                int col = ks * 64 + k0;
                float4 v = (eb + r < NN) ? ld4(g_x1 + (size_t)(eb + r) * 128 + col) : z4;
                float4 h;
                h.x = v.x * scs[col + 0] + shs[col + 0];
                h.y = v.y * scs[col + 1] + shs[col + 1];
                h.z = v.z * scs[col + 2] + shs[col + 2];
                h.w = v.w * scs[col + 3] + shs[col + 3];
                split_store(smc + OFF_AHI + r * EP2 + k0 * 2,
                            smc + OFF_ALO + r * EP2 + k0 * 2, h);
            }
        }
        {
            const uint32_t* bh = reinterpret_cast<const uint32_t*>(g_wf1t_hi) + colsec * 8192;
            const uint32_t* bl = reinterpret_cast<const uint32_t*>(g_wf1t_lo) + colsec * 8192;
            for (int t = tid; t < 4096; t += 512) {
                int n = t >> 5, k2 = t & 31;
                *reinterpret_cast<uint32_t*>(smc + OFF_BHI + n * EP2 + k2 * 4) = bh[n * 64 + ks * 32 + k2];
                *reinterpret_cast<uint32_t*>(smc + OFF_BLO + n * EP2 + k2 * 4) = bl[n * 64 + ks * 32 + k2];
            }
        }
        __syncthreads();

#pragma unroll
        for (int kk = 0; kk < 4; kk++) {
            uint32_t aH[4], aL[4];
            uint32_t aaddr = aBase + kk * 32;
            ldsm_x4(aH, aaddr);
            ldsm_x4(aL, aaddr + (OFF_ALO - OFF_AHI));
#pragma unroll
            for (int ntp = 0; ntp < 4; ntp++) {
                uint32_t bH[4], bL[4];
                uint32_t baddr = smb + OFF_BHI + (colhalf + ntp * 16 + bRowSel) * EP2
                               + kk * 32 + bColSel;
                ldsm_x4(bH, baddr);
                ldsm_x4(bL, baddr + (OFF_BLO - OFF_BHI));
                mma_bf16(acc[2 * ntp],     aH, &bH[0]);
                mma_bf16(acc[2 * ntp],     aH, &bL[0]);
                mma_bf16(acc[2 * ntp],     aL, &bH[0]);
                mma_bf16(acc[2 * ntp + 1], aH, &bH[2]);
                mma_bf16(acc[2 * ntp + 1], aH, &bL[2]);
                mma_bf16(acc[2 * ntp + 1], aL, &bH[2]);
            }
        }
    }

    {
        int r0 = slab + (lid >> 2);
        int cb2 = (lid & 3) * 2;
        bool ok0 = (eb + r0 < NN), ok1 = (eb + r0 + 8 < NN);
        float* d0 = g_mid + (size_t)(eb + r0) * 256 + colsec * 128 + colhalf;
        float* d1 = g_mid + (size_t)(eb + r0 + 8) * 256 + colsec * 128 + colhalf;
        const float* bp = g_biasf + colsec * 128 + colhalf;
#pragma unroll
        for (int nt = 0; nt < 8; nt++) {
            int c = nt * 8 + cb2;
            float b0 = bp[c], b1 = bp[c + 1];
            if (ok0) *reinterpret_cast<float2*>(d0 + c) =
                make_float2(fmaxf(acc[nt][0] + b0, 0.f), fmaxf(acc[nt][1] + b1, 0.f));
            if (ok1) *reinterpret_cast<float2*>(d1 + c) =
                make_float2(fmaxf(acc[nt][2] + b0, 0.f), fmaxf(acc[nt][3] + b1, 0.f));
        }
    }
}

// ===== K5b: FFN GEMM2: x2 = BN_n1(x1) + mid @ Wf2 + bf2; n2-stats ==========
__global__ __launch_bounds__(512, 2) void k_ffn2(
    const float* __restrict__ gn1, const float* __restrict__ ben1)
{
    extern __shared__ char smc[];
    const uint32_t smb = smem_u32(smc);
    float* scs = reinterpret_cast<float*>(smc + SM_GEMM_TOTAL);
    float* shs = scs + 128;
    const int tid = threadIdx.x;
    const int wid = tid >> 5, lid = tid & 31;
    const int eb = blockIdx.x * 128;
    const int slab = (wid >> 1) * 16;
    const int colhalf = (wid & 1) * 64;

    if (tid < 128) {
        float m = g_stats[512 + tid] * (1.f / NN);
        float v = g_stats[640 + tid] * (1.f / NN) - m * m;
        float sc = gn1[tid] * rsqrtf(v + 1e-5f);
        scs[tid] = sc;
        shs[tid] = ben1[tid] - m * sc;
    }
    __syncthreads();

    float acc[8][4];
#pragma unroll
    for (int i = 0; i < 8; i++)
#pragma unroll
        for (int j = 0; j < 4; j++) acc[i][j] = 0.f;

    const uint32_t aBase = smb + OFF_AHI + (slab + (lid & 15)) * EP2 + (lid >> 4) * 16;
    const uint32_t bRowSel = (lid & 7) + ((lid >> 4) << 3);
    const uint32_t bColSel = ((lid >> 3) & 1) * 16;

#pragma unroll 1
    for (int ks = 0; ks < 4; ks++) {
        if (ks) __syncthreads();
        {
            const float4 z4 = make_float4(0.f, 0.f, 0.f, 0.f);
            for (int t = tid; t < 2048; t += 512) {
                int r = t >> 4, c4 = t & 15, k0 = c4 * 4;
                float4 v = (eb + r < NN) ? ld4(g_mid + (size_t)(eb + r) * 256 + ks * 64 + k0) : z4;
                split_store(smc + OFF_AHI + r * EP2 + k0 * 2,
                            smc + OFF_ALO + r * EP2 + k0 * 2, v);
            }
        }
        {
            const uint32_t* bh = reinterpret_cast<const uint32_t*>(g_wf2t_hi);
            const uint32_t* bl = reinterpret_cast<const uint32_t*>(g_wf2t_lo);
            for (int t = tid; t < 4096; t += 512) {
                int n = t >> 5, k2 = t & 31;
                *reinterpret_cast<uint32_t*>(smc + OFF_BHI + n * EP2 + k2 * 4) = bh[n * 128 + ks * 32 + k2];
                *reinterpret_cast<uint32_t*>(smc + OFF_BLO + n * EP2 + k2 * 4) = bl[n * 128 + ks * 32 + k2];
            }
        }
        __syncthreads();

#pragma unroll
        for (int kk = 0; kk < 4; kk++) {
            uint32_t aH[4], aL[4];
            uint32_t aaddr = aBase + kk * 32;
            ldsm_x4(aH, aaddr);
            ldsm_x4(aL, aaddr + (OFF_ALO - OFF_AHI));
#pragma unroll
            for (int ntp = 0; ntp < 4; ntp++) {
                uint32_t bH[4], bL[4];
                uint32_t baddr = smb + OFF_BHI + (colhalf + ntp * 16 + bRowSel) * EP2
                               + kk * 32 + bColSel;
                ldsm_x4(bH, baddr);
                ldsm_x4(bL, baddr + (OFF_BLO - OFF_BHI));
                mma_bf16(acc[2 * ntp],     aH, &bH[0]);
                mma_bf16(acc[2 * ntp],     aH, &bL[0]);
                mma_bf16(acc[2 * ntp],     aL, &bH[0]);
                mma_bf16(acc[2 * ntp + 1], aH, &bH[2]);
                mma_bf16(acc[2 * ntp + 1], aH, &bL[2]);
                mma_bf16(acc[2 * ntp + 1], aL, &bH[2]);
            }
        }
    }
    __syncthreads();   // A/B regions now dead; reuse for stats

    float* sS = reinterpret_cast<float*>(smc + OFF_AHI);
    float* sQ = sS + 128;
    if (tid < 128) { sS[tid] = 0.f; sQ[tid] = 0.f; }
    __syncthreads();

    {
        int r0 = slab + (lid >> 2);
        int cb2 = (lid & 3) * 2;
        bool ok0 = (eb + r0 < NN), ok1 = (eb + r0 + 8 < NN);
#pragma unroll
        for (int nt = 0; nt < 8; nt++) {
            int c = colhalf + nt * 8 + cb2;
            float b0 = g_biasf[256 + c], b1 = g_biasf[256 + c + 1];
            float s0 = 0.f, q0 = 0.f, s1 = 0.f, q1 = 0.f;
            if (ok0) {
                int gr = eb + r0;
                float h0 = g_x1[(size_t)gr * 128 + c] * scs[c] + shs[c];
                float h1 = g_x1[(size_t)gr * 128 + c + 1] * scs[c + 1] + shs[c + 1];
                float o0 = h0 + acc[nt][0] + b0;
                float o1 = h1 + acc[nt][1] + b1;
                *reinterpret_cast<float2*>(g_x2 + (size_t)gr * 128 + c) = make_float2(o0, o1);
                s0 += o0; q0 += o0 * o0; s1 += o1; q1 += o1 * o1;
            }
            if (ok1) {
                int gr = eb + r0 + 8;
                float h0 = g_x1[(size_t)gr * 128 + c] * scs[c] + shs[c];
                float h1 = g_x1[(size_t)gr * 128 + c + 1] * scs[c + 1] + shs[c + 1];
                float o0 = h0 + acc[nt][2] + b0;
                float o1 = h1 + acc[nt][3] + b1;
                *reinterpret_cast<float2*>(g_x2 + (size_t)gr * 128 + c) = make_float2(o0, o1);
                s0 += o0; q0 += o0 * o0; s1 += o1; q1 += o1 * o1;
            }
            atomicAdd(&sS[c], s0);     atomicAdd(&sQ[c], q0);
            atomicAdd(&sS[c + 1], s1); atomicAdd(&sQ[c + 1], q1);
        }
    }
    __syncthreads();
    if (tid < 128) {
        atomicAdd(&g_stats[768 + tid], sS[tid]);
        atomicAdd(&g_stats[896 + tid], sQ[tid]);
    }
}

// ===== K6: x_out = BN_n2(x2) ================================================
__global__ void k_out_x(float* __restrict__ out,
                        const float* __restrict__ gn2, const float* __restrict__ ben2)
{
    int idx = blockIdx.x * blockDim.x + threadIdx.x;
    if (idx >= NN * 32) return;
    int c0 = (idx & 31) * 4;
    float4 v = reinterpret_cast<const float4*>(g_x2)[idx];
    float val[4] = { v.x, v.y, v.z, v.w };
    float o[4];
#pragma unroll
    for (int j = 0; j < 4; j++) {
        int c = c0 + j;
        float m = g_stats[768 + c] * (1.f / NN);
        float var = g_stats[896 + c] * (1.f / NN) - m * m;
        o[j] = gn2[c] * (val[j] - m) * rsqrtf(var + 1e-5f) + ben2[c];
    }
    reinterpret_cast<float4*>(out)[idx] = make_float4(o[0], o[1], o[2], o[3]);
}

// ===== K7: e_out = e + relu(BN_e(e_ij)); fully streaming ====================
__global__ void k_out_e(const float* __restrict__ e, float* __restrict__ out,
                        const float* __restrict__ ge, const float* __restrict__ bee)
{
    size_t idx = (size_t)blockIdx.x * blockDim.x + threadIdx.x;
    if (idx >= (size_t)NE * 32) return;
    int c0 = ((int)(idx & 31)) * 4;
    float4 v = ldcs4(g_eij + idx * 4);
    float4 ev = ldcs4(e + idx * 4);
    float val[4] = { v.x, v.y, v.z, v.w };
    float res[4] = { ev.x, ev.y, ev.z, ev.w };
    float o[4];
#pragma unroll
    for (int j = 0; j < 4; j++) {
        int c = c0 + j;
        float m = g_stats[c] * (1.f / NE);
        float var = g_stats[128 + c] * (1.f / NE) - m * m;
        float bn = ge[c] * (val[j] - m) * rsqrtf(var + 1e-5f) + bee[c];
        o[j] = res[j] + fmaxf(bn, 0.f);
    }
    stcs4(out + (size_t)NN * DD + idx * 4, make_float4(o[0], o[1], o[2], o[3]));
}

// ===== launch ===============================================================
extern "C" void kernel_launch(void* const* d_in, const int* in_sizes, int n_in,
                              void* d_out, int out_size)
{
    const float* x   = (const float*)d_in[0];
    const float* e   = (const float*)d_in[1];
    const int*   eidx= (const int*)  d_in[2];
    const float* WA  = (const float*)d_in[3];  const float* bA  = (const float*)d_in[4];
    const float* WB  = (const float*)d_in[5];  const float* bB  = (const float*)d_in[6];
    const float* WC  = (const float*)d_in[7];  const float* bC  = (const float*)d_in[8];
    const float* WD  = (const float*)d_in[9];  const float* bD  = (const float*)d_in[10];
    const float* WE  = (const float*)d_in[11]; const float* bE  = (const float*)d_in[12];
    const float* gx  = (const float*)d_in[13]; const float* bex = (const float*)d_in[14];
    const float* ge  = (const float*)d_in[15]; const float* bee = (const float*)d_in[16];
    const float* Wf1 = (const float*)d_in[17]; const float* bf1 = (const float*)d_in[18];
    const float* Wf2 = (const float*)d_in[19]; const float* bf2 = (const float*)d_in[20];
    const float* gn1 = (const float*)d_in[21]; const float* ben1= (const float*)d_in[22];
    const float* gn2 = (const float*)d_in[23]; const float* ben2= (const float*)d_in[24];
    float* out = (float*)d_out;

    static cudaStream_t s2 = nullptr;
    static cudaEvent_t evFork = nullptr, evJoin = nullptr;
    if (!s2) {
        cudaStreamCreateWithFlags(&s2, cudaStreamNonBlocking);
        cudaEventCreateWithFlags(&evFork, cudaEventDisableTiming);
        cudaEventCreateWithFlags(&evJoin, cudaEventDisableTiming);
    }

    void *p_num, *p_den, *p_st;
    cudaGetSymbolAddress(&p_num, g_num);
    cudaGetSymbolAddress(&p_den, g_den);
    cudaGetSymbolAddress(&p_st,  g_stats);
    cudaMemsetAsync(p_num, 0, sizeof(float) * NN * DD, 0);
    cudaMemsetAsync(p_den, 0, sizeof(float) * NN * DD, 0);
    cudaMemsetAsync(p_st,  0, sizeof(float) * 8 * DD, 0);

    cudaFuncSetAttribute(k_node_gemm_mma, cudaFuncAttributeMaxDynamicSharedMemorySize, SM_GEMM_TOTAL);
    cudaFuncSetAttribute(k_edge_fused,    cudaFuncAttributeMaxDynamicSharedMemorySize, SM_GEMM_TOTAL);
    cudaFuncSetAttribute(k_ffn1,          cudaFuncAttributeMaxDynamicSharedMemorySize, SM_FFN_TOTAL);
    cudaFuncSetAttribute(k_ffn2,          cudaFuncAttributeMaxDynamicSharedMemorySize, SM_FFN_TOTAL);

    k_prep_w4<<<256, 256>>>(WA, WB, WD, WE, bA, bB, bD, bE);          // 0
    k_node_gemm_mma<<<dim3(NBLK_N, 4), 512, SM_GEMM_TOTAL>>>(x);      // 1
    k_prep_wct<<<64, 256>>>(WC);                                      // 2
    k_edge_fused<<<NBLK_E, 512, SM_GEMM_TOTAL>>>(e, eidx, bC);        // 3 <- profiled slot

    // fork: e_out path runs concurrently with the node chain
    cudaEventRecord(evFork, 0);
    cudaStreamWaitEvent(s2, evFork, 0);
    k_out_e<<<(int)(((size_t)NE * 32 + 255) / 256), 256, 0, s2>>>(e, out, ge, bee);
    cudaEventRecord(evJoin, s2);

    k_node_t2<<<(NN + 63) / 64, 256>>>();
    k_node_x12<<<(NN + 63) / 64, 256>>>(x, gx, bex);
    k_prep_wf<<<256, 256>>>(Wf1, Wf2, bf1, bf2);
    k_ffn1<<<dim3(NBLK_N, 2), 512, SM_FFN_TOTAL>>>(gn1, ben1);
    k_ffn2<<<NBLK_N, 512, SM_FFN_TOTAL>>>(gn1, ben1);
    k_out_x<<<(NN * 32 + 255) / 256, 256>>>(out, gn2, ben2);

    // join: main stream completes only after e_out is done
    cudaStreamWaitEvent(0, evJoin, 0);
}

// round 16
// speedup vs baseline: 1.0368x; 1.0368x over previous
#include <cuda_runtime.h>
#include <cuda_bf16.h>
#include <math.h>
#include <stdint.h>

#define NN 50000
#define NE 600000
#define DD 128
#define NBLK_E ((NE + 127) / 128)   // 4688
#define NBLK_N ((NN + 127) / 128)   // 391

// ---------------- device scratch ----------------
__device__ __align__(16) float g_nodeABDE[NN * 512];   // [Ax|Bx|Dx|Ex]
__device__ __align__(16) float g_eij[(size_t)NE * DD];
__device__ __align__(16) float g_num[NN * DD];
__device__ __align__(16) float g_den[NN * DD];
__device__ __align__(16) float g_t[NN * DD];
__device__ __align__(16) float g_x1[NN * DD];
__device__ __align__(16) float g_x2[NN * DD];
__device__ __align__(16) float g_mid[NN * 256];
// [0]=e_sum [128]=e_sq [256]=x_sum [384]=x_sq [512]=n1_sum [640]=n1_sq [768]=n2_sum [896]=n2_sq
__device__ float g_stats[8 * DD];
// pre-split weights (transposed, [n][k] bf16 hi/lo)
__device__ __align__(16) __nv_bfloat16 g_wct_hi[128 * 128];
__device__ __align__(16) __nv_bfloat16 g_wct_lo[128 * 128];
__device__ __align__(16) __nv_bfloat16 g_w4t_hi[4 * 128 * 128];
__device__ __align__(16) __nv_bfloat16 g_w4t_lo[4 * 128 * 128];
__device__ __align__(16) __nv_bfloat16 g_wf1t_hi[256 * 128];
__device__ __align__(16) __nv_bfloat16 g_wf1t_lo[256 * 128];
__device__ __align__(16) __nv_bfloat16 g_wf2t_hi[128 * 256];
__device__ __align__(16) __nv_bfloat16 g_wf2t_lo[128 * 256];
__device__ float g_bias4[512];
__device__ float g_biasf[384];   // [0:256)=bf1, [256:384)=bf2

static __device__ __forceinline__ float4 ld4(const float* p) {
    return *reinterpret_cast<const float4*>(p);
}
static __device__ __forceinline__ void st4(float* p, float4 v) {
    *reinterpret_cast<float4*>(p) = v;
}
static __device__ __forceinline__ uint32_t smem_u32(const void* p) {
    uint32_t a;
    asm("{ .reg .u64 t; cvta.to.shared.u64 t, %1; cvt.u32.u64 %0, t; }" : "=r"(a) : "l"(p));
    return a;
}
static __device__ __forceinline__ void ldsm_x4(uint32_t* r, uint32_t addr) {
    asm volatile("ldmatrix.sync.aligned.m8n8.x4.shared.b16 {%0,%1,%2,%3}, [%4];"
                 : "=r"(r[0]), "=r"(r[1]), "=r"(r[2]), "=r"(r[3]) : "r"(addr));
}
static __device__ __forceinline__ void mma_bf16(float* d, const uint32_t* a, const uint32_t* b) {
    asm volatile("mma.sync.aligned.m16n8k16.row.col.f32.bf16.bf16.f32 "
                 "{%0,%1,%2,%3}, {%4,%5,%6,%7}, {%8,%9}, {%0,%1,%2,%3};"
                 : "+f"(d[0]), "+f"(d[1]), "+f"(d[2]), "+f"(d[3])
                 : "r"(a[0]), "r"(a[1]), "r"(a[2]), "r"(a[3]), "r"(b[0]), "r"(b[1]));
}
static __device__ __forceinline__ void split_store(char* hi, char* lo, float4 v) {
    __nv_bfloat16 h0 = __float2bfloat16(v.x);
    __nv_bfloat16 h1 = __float2bfloat16(v.y);
    __nv_bfloat16 h2 = __float2bfloat16(v.z);
    __nv_bfloat16 h3 = __float2bfloat16(v.w);
    __nv_bfloat16 l0 = __float2bfloat16(v.x - __bfloat162float(h0));
    __nv_bfloat16 l1 = __float2bfloat16(v.y - __bfloat162float(h1));
    __nv_bfloat16 l2 = __float2bfloat16(v.z - __bfloat162float(h2));
    __nv_bfloat16 l3 = __float2bfloat16(v.w - __bfloat162float(h3));
    *reinterpret_cast<__nv_bfloat162*>(hi)     = __nv_bfloat162(h0, h1);
    *reinterpret_cast<__nv_bfloat162*>(hi + 4) = __nv_bfloat162(h2, h3);
    *reinterpret_cast<__nv_bfloat162*>(lo)     = __nv_bfloat162(l0, l1);
    *reinterpret_cast<__nv_bfloat162*>(lo + 4) = __nv_bfloat162(l2, l3);
}

// smem layout for gemm kernels: K-split halves, 64 bf16 cols + 8 pad = 144B pitch
#define EP2      144
#define OFF_AHI  0
#define OFF_ALO  18432
#define OFF_BHI  36864
#define OFF_BLO  55296
#define SM_GEMM_TOTAL 73728
#define SM_FFN_TOTAL  74752   // + scs/shs (2*128 f32)

// ===== K0a: WC -> WC^T bf16 hi/lo ==========================================
__global__ void k_prep_wct(const float* __restrict__ WC)
{
    int idx = blockIdx.x * 256 + threadIdx.x;     // 16384
    int n = idx >> 7, k = idx & 127;
    float w = WC[k * 128 + n];
    __nv_bfloat16 h = __float2bfloat16(w);
    g_wct_hi[n * 128 + k] = h;
    g_wct_lo[n * 128 + k] = __float2bfloat16(w - __bfloat162float(h));
}

// ===== K0b: [WA|WB|WD|WE]^T -> bf16 hi/lo + bias pack ======================
__global__ void k_prep_w4(
    const float* __restrict__ WA, const float* __restrict__ WB,
    const float* __restrict__ WD, const float* __restrict__ WE,
    const float* __restrict__ bA, const float* __restrict__ bB,
    const float* __restrict__ bD, const float* __restrict__ bE)
{
    int idx = blockIdx.x * 256 + threadIdx.x;     // 65536
    int mat = idx >> 14, rem = idx & 16383;
    int n = rem >> 7, k = rem & 127;
    const float* W = (mat == 0) ? WA : (mat == 1) ? WB : (mat == 2) ? WD : WE;
    float w = W[k * 128 + n];
    __nv_bfloat16 h = __float2bfloat16(w);
    g_w4t_hi[idx] = h;
    g_w4t_lo[idx] = __float2bfloat16(w - __bfloat162float(h));
    if (k == 0) {
        const float* b = (mat == 0) ? bA : (mat == 1) ? bB : (mat == 2) ? bD : bE;
        g_bias4[mat * 128 + n] = b[n];
    }
}

// ===== K0c: Wf1^T, Wf2^T -> bf16 hi/lo + bias pack =========================
__global__ void k_prep_wf(
    const float* __restrict__ Wf1, const float* __restrict__ Wf2,
    const float* __restrict__ bf1, const float* __restrict__ bf2)
{
    int idx = blockIdx.x * 256 + threadIdx.x;     // 65536
    if (idx < 32768) {
        int n = idx >> 7, k = idx & 127;
        float w = Wf1[k * 256 + n];
        __nv_bfloat16 h = __float2bfloat16(w);
        g_wf1t_hi[n * 128 + k] = h;
        g_wf1t_lo[n * 128 + k] = __float2bfloat16(w - __bfloat162float(h));
        if (k == 0) g_biasf[n] = bf1[n];
    } else {
        int rem = idx - 32768;
        int n = rem >> 8, k = rem & 255;
        float w = Wf2[k * 128 + n];
        __nv_bfloat16 h = __float2bfloat16(w);
        g_wf2t_hi[n * 256 + k] = h;
        g_wf2t_lo[n * 256 + k] = __float2bfloat16(w - __bfloat162float(h));
        if (k == 0) g_biasf[256 + n] = bf2[n];
    }
}

// ===== K1: node 4-GEMM via mma.sync bf16 split =============================
__global__ __launch_bounds__(512, 2) void k_node_gemm_mma(const float* __restrict__ x)
{
    extern __shared__ char smc[];
    const uint32_t smb = smem_u32(smc);
    const int tid = threadIdx.x;
    const int wid = tid >> 5, lid = tid & 31;
    const int eb = blockIdx.x * 128;
    const int mat = blockIdx.y;
    const int slab = (wid >> 1) * 16;
    const int colhalf = (wid & 1) * 64;

    float acc[8][4];
#pragma unroll
    for (int i = 0; i < 8; i++)
#pragma unroll
        for (int j = 0; j < 4; j++) acc[i][j] = 0.f;

    const uint32_t aBase = smb + OFF_AHI + (slab + (lid & 15)) * EP2 + (lid >> 4) * 16;
    const uint32_t bRowSel = (lid & 7) + ((lid >> 4) << 3);
    const uint32_t bColSel = ((lid >> 3) & 1) * 16;

#pragma unroll 1
    for (int ks = 0; ks < 2; ks++) {
        if (ks) __syncthreads();
        {
            const float4 z4 = make_float4(0.f, 0.f, 0.f, 0.f);
            for (int t = tid; t < 2048; t += 512) {
                int r = t >> 4, c4 = t & 15, k0 = c4 * 4;
                float4 v = (eb + r < NN) ? ld4(x + (size_t)(eb + r) * 128 + ks * 64 + k0) : z4;
                split_store(smc + OFF_AHI + r * EP2 + k0 * 2,
                            smc + OFF_ALO + r * EP2 + k0 * 2, v);
            }
        }
        {
            const uint32_t* bh = reinterpret_cast<const uint32_t*>(g_w4t_hi) + mat * 8192;
            const uint32_t* bl = reinterpret_cast<const uint32_t*>(g_w4t_lo) + mat * 8192;
            for (int t = tid; t < 4096; t += 512) {
                int n = t >> 5, k2 = t & 31;
                *reinterpret_cast<uint32_t*>(smc + OFF_BHI + n * EP2 + k2 * 4) = bh[n * 64 + ks * 32 + k2];
                *reinterpret_cast<uint32_t*>(smc + OFF_BLO + n * EP2 + k2 * 4) = bl[n * 64 + ks * 32 + k2];
            }
        }
        __syncthreads();

#pragma unroll
        for (int kk = 0; kk < 4; kk++) {
            uint32_t aH[4], aL[4];
            uint32_t aaddr = aBase + kk * 32;
            ldsm_x4(aH, aaddr);
            ldsm_x4(aL, aaddr + (OFF_ALO - OFF_AHI));
#pragma unroll
            for (int ntp = 0; ntp < 4; ntp++) {
                uint32_t bH[4], bL[4];
                uint32_t baddr = smb + OFF_BHI + (colhalf + ntp * 16 + bRowSel) * EP2
                               + kk * 32 + bColSel;
                ldsm_x4(bH, baddr);
                ldsm_x4(bL, baddr + (OFF_BLO - OFF_BHI));
                mma_bf16(acc[2 * ntp],     aH, &bH[0]);
                mma_bf16(acc[2 * ntp],     aH, &bL[0]);
                mma_bf16(acc[2 * ntp],     aL, &bH[0]);
                mma_bf16(acc[2 * ntp + 1], aH, &bH[2]);
                mma_bf16(acc[2 * ntp + 1], aH, &bL[2]);
                mma_bf16(acc[2 * ntp + 1], aL, &bH[2]);
            }
        }
    }

    {
        int r0 = slab + (lid >> 2);
        int cb2 = (lid & 3) * 2;
        bool ok0 = (eb + r0 < NN), ok1 = (eb + r0 + 8 < NN);
        float* d0 = g_nodeABDE + (size_t)(eb + r0) * 512 + mat * 128 + colhalf;
        float* d1 = g_nodeABDE + (size_t)(eb + r0 + 8) * 512 + mat * 128 + colhalf;
        const float* bp = g_bias4 + mat * 128 + colhalf;
#pragma unroll
        for (int nt = 0; nt < 8; nt++) {
            int c = nt * 8 + cb2;
            float b0 = bp[c], b1 = bp[c + 1];
            if (ok0) *reinterpret_cast<float2*>(d0 + c) = make_float2(acc[nt][0] + b0, acc[nt][1] + b1);
            if (ok1) *reinterpret_cast<float2*>(d1 + c) = make_float2(acc[nt][2] + b0, acc[nt][3] + b1);
        }
    }
}

// ===== K2: FUSED edge GEMM + epilogue (scatter + sigma + e-stats) ==========
__global__ __launch_bounds__(512, 2) void k_edge_fused(
    const float* __restrict__ e, const int* __restrict__ eidx,
    const float* __restrict__ bC)
{
    extern __shared__ char smc[];
    const uint32_t smb = smem_u32(smc);
    const int tid = threadIdx.x;
    const int wid = tid >> 5, lid = tid & 31;
    const int eb = blockIdx.x * 128;
    const int slab = (wid >> 1) * 16;
    const int colhalf = (wid & 1) * 64;

    float acc[8][4];
#pragma unroll
    for (int i = 0; i < 8; i++)
#pragma unroll
        for (int j = 0; j < 4; j++) acc[i][j] = 0.f;

    const uint32_t aBase = smb + OFF_AHI + (slab + (lid & 15)) * EP2 + (lid >> 4) * 16;
    const uint32_t bRowSel = (lid & 7) + ((lid >> 4) << 3);
    const uint32_t bColSel = ((lid >> 3) & 1) * 16;

#pragma unroll 1
    for (int ks = 0; ks < 2; ks++) {
        if (ks) __syncthreads();
        {
            const float4 z4 = make_float4(0.f, 0.f, 0.f, 0.f);
            for (int t = tid; t < 2048; t += 512) {
                int r = t >> 4, c4 = t & 15, k0 = c4 * 4;
                float4 v = (eb + r < NE) ? ld4(e + (size_t)(eb + r) * 128 + ks * 64 + k0) : z4;
                split_store(smc + OFF_AHI + r * EP2 + k0 * 2,
                            smc + OFF_ALO + r * EP2 + k0 * 2, v);
            }
        }
        {
            const uint32_t* bh = reinterpret_cast<const uint32_t*>(g_wct_hi);
            const uint32_t* bl = reinterpret_cast<const uint32_t*>(g_wct_lo);
            for (int t = tid; t < 4096; t += 512) {
                int n = t >> 5, k2 = t & 31;
                *reinterpret_cast<uint32_t*>(smc + OFF_BHI + n * EP2 + k2 * 4) = bh[n * 64 + ks * 32 + k2];
                *reinterpret_cast<uint32_t*>(smc + OFF_BLO + n * EP2 + k2 * 4) = bl[n * 64 + ks * 32 + k2];
            }
        }
        __syncthreads();

#pragma unroll
        for (int kk = 0; kk < 4; kk++) {
            uint32_t aH[4], aL[4];
            uint32_t aaddr = aBase + kk * 32;
            ldsm_x4(aH, aaddr);
            ldsm_x4(aL, aaddr + (OFF_ALO - OFF_AHI));
#pragma unroll
            for (int ntp = 0; ntp < 4; ntp++) {
                uint32_t bH[4], bL[4];
                uint32_t baddr = smb + OFF_BHI + (colhalf + ntp * 16 + bRowSel) * EP2
                               + kk * 32 + bColSel;
                ldsm_x4(bH, baddr);
                ldsm_x4(bL, baddr + (OFF_BLO - OFF_BHI));
                mma_bf16(acc[2 * ntp],     aH, &bH[0]);
                mma_bf16(acc[2 * ntp],     aH, &bL[0]);
                mma_bf16(acc[2 * ntp],     aL, &bH[0]);
                mma_bf16(acc[2 * ntp + 1], aH, &bH[2]);
                mma_bf16(acc[2 * ntp + 1], aH, &bL[2]);
                mma_bf16(acc[2 * ntp + 1], aL, &bH[2]);
            }
        }
    }
    __syncthreads();   // mainloop done reading A/B smem

    // ---- stage Ce into smem (pitch 130 f32) ----
    float* Dsm = reinterpret_cast<float*>(smc);
    {
        int r0 = slab + (lid >> 2);
        int cb2 = (lid & 3) * 2;
#pragma unroll
        for (int nt = 0; nt < 8; nt++) {
            int c = colhalf + nt * 8 + cb2;
            *reinterpret_cast<float2*>(&Dsm[r0 * 130 + c])       = make_float2(acc[nt][0], acc[nt][1]);
            *reinterpret_cast<float2*>(&Dsm[(r0 + 8) * 130 + c]) = make_float2(acc[nt][2], acc[nt][3]);
        }
    }
    __syncthreads();

    // ---- epilogue ----
    const int tx = tid & 15, ty = tid >> 4;
    float4 bc0 = ld4(bC + tx * 4), bc1 = ld4(bC + 64 + tx * 4);
    float ssum[8], ssq[8];
#pragma unroll
    for (int j = 0; j < 8; j++) { ssum[j] = 0.f; ssq[j] = 0.f; }

    const float4* nb = reinterpret_cast<const float4*>(g_nodeABDE);
    float4* numb = reinterpret_cast<float4*>(g_num);
    float4* denb = reinterpret_cast<float4*>(g_den);
    float4* eijb = reinterpret_cast<float4*>(g_eij);

    // batch the index loads for all 4 edges (MLP)
    int srcs[4], dsts[4];
#pragma unroll
    for (int i = 0; i < 4; i++) {
        int eg = eb + ty * 4 + i;
        srcs[i] = (eg < NE) ? eidx[eg] : 0;
        dsts[i] = (eg < NE) ? eidx[NE + eg] : 0;
    }

#pragma unroll
    for (int i = 0; i < 4; i++) {
        int lr = ty * 4 + i;
        int eg = eb + lr;
        if (eg >= NE) continue;
        int src = srcs[i];
        int dst = dsts[i];
#pragma unroll
        for (int cc = 0; cc < 2; cc++) {
            int c4 = tx + cc * 16;
            int col = c4 * 4;
            float a0 = Dsm[lr * 130 + col + 0];
            float a1 = Dsm[lr * 130 + col + 1];
            float a2 = Dsm[lr * 130 + col + 2];
            float a3 = Dsm[lr * 130 + col + 3];
            float4 dx = nb[(size_t)dst * 128 + 64 + c4];
            float4 ex = nb[(size_t)src * 128 + 96 + c4];
            float4 bx = nb[(size_t)src * 128 + 32 + c4];
            float4 bc = cc ? bc1 : bc0;
            float4 eij;
            eij.x = a0 + bc.x + dx.x + ex.x;
            eij.y = a1 + bc.y + dx.y + ex.y;
            eij.z = a2 + bc.z + dx.z + ex.z;
            eij.w = a3 + bc.w + dx.w + ex.w;
            eijb[(size_t)eg * 32 + c4] = eij;
            float4 sg;
            sg.x = 1.f / (1.f + __expf(-eij.x));
            sg.y = 1.f / (1.f + __expf(-eij.y));
            sg.z = 1.f / (1.f + __expf(-eij.z));
            sg.w = 1.f / (1.f + __expf(-eij.w));
            atomicAdd(numb + (size_t)dst * 32 + c4,
                      make_float4(sg.x * bx.x, sg.y * bx.y, sg.z * bx.z, sg.w * bx.w));
            atomicAdd(denb + (size_t)dst * 32 + c4, sg);
            ssum[cc * 4 + 0] += eij.x; ssq[cc * 4 + 0] += eij.x * eij.x;
            ssum[cc * 4 + 1] += eij.y; ssq[cc * 4 + 1] += eij.y * eij.y;
            ssum[cc * 4 + 2] += eij.z; ssq[cc * 4 + 2] += eij.z * eij.z;
            ssum[cc * 4 + 3] += eij.w; ssq[cc * 4 + 3] += eij.w * eij.w;
        }
    }
    __syncthreads();   // Dsm dead; reuse for stats reduce

    float* redS = reinterpret_cast<float*>(smc);            // 32 x 128
    float* redQ = reinterpret_cast<float*>(smc) + 4096;     // 32 x 128
#pragma unroll
    for (int cc = 0; cc < 2; cc++)
#pragma unroll
        for (int j = 0; j < 4; j++) {
            redS[ty * 128 + cc * 64 + tx * 4 + j] = ssum[cc * 4 + j];
            redQ[ty * 128 + cc * 64 + tx * 4 + j] = ssq[cc * 4 + j];
        }
    __syncthreads();
    if (tid < 128) {
        float s = 0.f, q = 0.f;
#pragma unroll
        for (int t = 0; t < 32; t++) { s += redS[t * 128 + tid]; q += redQ[t * 128 + tid]; }
        atomicAdd(&g_stats[tid], s);
        atomicAdd(&g_stats[128 + tid], q);
    }
}

// ===== K3: t = Ax + num/(den+eps); x-stats =================================
__global__ __launch_bounds__(256) void k_node_t2()
{
    __shared__ float sS[8 * 128], sQ[8 * 128];
    const int tid = threadIdx.x;
    const int c4 = tid & 31, g = tid >> 5;
    const int rb = blockIdx.x * 64;
    float s[4] = {0, 0, 0, 0}, q[4] = {0, 0, 0, 0};
#pragma unroll
    for (int p = 0; p < 8; p++) {
        int r = rb + p * 8 + g;
        if (r < NN) {
            float4 ax = ld4(g_nodeABDE + (size_t)r * 512 + c4 * 4);
            float4 nu = ld4(g_num + (size_t)r * 128 + c4 * 4);
            float4 de = ld4(g_den + (size_t)r * 128 + c4 * 4);
            float4 t;
            t.x = ax.x + nu.x / (de.x + 1e-6f);
            t.y = ax.y + nu.y / (de.y + 1e-6f);
            t.z = ax.z + nu.z / (de.z + 1e-6f);
            t.w = ax.w + nu.w / (de.w + 1e-6f);
            st4(g_t + (size_t)r * 128 + c4 * 4, t);
            s[0] += t.x; q[0] += t.x * t.x;
            s[1] += t.y; q[1] += t.y * t.y;
            s[2] += t.z; q[2] += t.z * t.z;
            s[3] += t.w; q[3] += t.w * t.w;
        }
    }
#pragma unroll
    for (int j = 0; j < 4; j++) { sS[g * 128 + c4 * 4 + j] = s[j]; sQ[g * 128 + c4 * 4 + j] = q[j]; }
    __syncthreads();
    if (tid < 128) {
        float a = 0.f, b = 0.f;
#pragma unroll
        for (int t = 0; t < 8; t++) { a += sS[t * 128 + tid]; b += sQ[t * 128 + tid]; }
        atomicAdd(&g_stats[256 + tid], a);
        atomicAdd(&g_stats[384 + tid], b);
    }
}

// ===== K4: x1 = x + relu(BN_x(t)); n1-stats ================================
__global__ __launch_bounds__(256) void k_node_x12(
    const float* __restrict__ x,
    const float* __restrict__ gx, const float* __restrict__ bex)
{
    __shared__ float sS[8 * 128], sQ[8 * 128];
    const int tid = threadIdx.x;
    const int c4 = tid & 31, g = tid >> 5;
    const int rb = blockIdx.x * 64;
    float sc[4], sh[4];
#pragma unroll
    for (int j = 0; j < 4; j++) {
        int c = c4 * 4 + j;
        float m = g_stats[256 + c] * (1.f / NN);
        float v = g_stats[384 + c] * (1.f / NN) - m * m;
        sc[j] = gx[c] * rsqrtf(v + 1e-5f);
        sh[j] = bex[c] - m * sc[j];
    }
    float s[4] = {0, 0, 0, 0}, q[4] = {0, 0, 0, 0};
#pragma unroll
    for (int p = 0; p < 8; p++) {
        int r = rb + p * 8 + g;
        if (r < NN) {
            float4 t = ld4(g_t + (size_t)r * 128 + c4 * 4);
            float4 xv = ld4(x + (size_t)r * 128 + c4 * 4);
            float4 o;
            o.x = xv.x + fmaxf(t.x * sc[0] + sh[0], 0.f);
            o.y = xv.y + fmaxf(t.y * sc[1] + sh[1], 0.f);
            o.z = xv.z + fmaxf(t.z * sc[2] + sh[2], 0.f);
            o.w = xv.w + fmaxf(t.w * sc[3] + sh[3], 0.f);
            st4(g_x1 + (size_t)r * 128 + c4 * 4, o);
            s[0] += o.x; q[0] += o.x * o.x;
            s[1] += o.y; q[1] += o.y * o.y;
            s[2] += o.z; q[2] += o.z * o.z;
            s[3] += o.w; q[3] += o.w * o.w;
        }
    }
#pragma unroll
    for (int j = 0; j < 4; j++) { sS[g * 128 + c4 * 4 + j] = s[j]; sQ[g * 128 + c4 * 4 + j] = q[j]; }
    __syncthreads();
    if (tid < 128) {
        float a = 0.f, b = 0.f;
#pragma unroll
        for (int t = 0; t < 8; t++) { a += sS[t * 128 + tid]; b += sQ[t * 128 + tid]; }
        atomicAdd(&g_stats[512 + tid], a);
        atomicAdd(&g_stats[640 + tid], b);
    }
}

// ===== K5a: FFN GEMM1: mid = relu(BN_n1(x1) @ Wf1 + bf1) ===================
__global__ __launch_bounds__(512, 2) void k_ffn1(
    const float* __restrict__ gn1, const float* __restrict__ ben1)
{
    extern __shared__ char smc[];
    const uint32_t smb = smem_u32(smc);
    float* scs = reinterpret_cast<float*>(smc + SM_GEMM_TOTAL);
    float* shs = scs + 128;
    const int tid = threadIdx.x;
    const int wid = tid >> 5, lid = tid & 31;
    const int eb = blockIdx.x * 128;
    const int colsec = blockIdx.y;
    const int slab = (wid >> 1) * 16;
    const int colhalf = (wid & 1) * 64;

    if (tid < 128) {
        float m = g_stats[512 + tid] * (1.f / NN);
        float v = g_stats[640 + tid] * (1.f / NN) - m * m;
        float sc = gn1[tid] * rsqrtf(v + 1e-5f);
        scs[tid] = sc;
        shs[tid] = ben1[tid] - m * sc;
    }
    __syncthreads();

    float acc[8][4];
#pragma unroll
    for (int i = 0; i < 8; i++)
#pragma unroll
        for (int j = 0; j < 4; j++) acc[i][j] = 0.f;

    const uint32_t aBase = smb + OFF_AHI + (slab + (lid & 15)) * EP2 + (lid >> 4) * 16;
    const uint32_t bRowSel = (lid & 7) + ((lid >> 4) << 3);
    const uint32_t bColSel = ((lid >> 3) & 1) * 16;

#pragma unroll 1
    for (int ks = 0; ks < 2; ks++) {
        if (ks) __syncthreads();
        {
            const float4 z4 = make_float4(0.f, 0.f, 0.f, 0.f);
            for (int t = tid; t < 2048; t += 512) {
                int r = t >> 4, c4 = t & 15, k0 = c4 * 4;
                int col = ks * 64 + k0;
                float4 v = (eb + r < NN) ? ld4(g_x1 + (size_t)(eb + r) * 128 + col) : z4;
                float4 h;
                h.x = v.x * scs[col + 0] + shs[col + 0];
                h.y = v.y * scs[col + 1] + shs[col + 1];
                h.z = v.z * scs[col + 2] + shs[col + 2];
                h.w = v.w * scs[col + 3] + shs[col + 3];
                split_store(smc + OFF_AHI + r * EP2 + k0 * 2,
                            smc + OFF_ALO + r * EP2 + k0 * 2, h);
            }
        }
        {
            const uint32_t* bh = reinterpret_cast<const uint32_t*>(g_wf1t_hi) + colsec * 8192;
            const uint32_t* bl = reinterpret_cast<const uint32_t*>(g_wf1t_lo) + colsec * 8192;
            for (int t = tid; t < 4096; t += 512) {
                int n = t >> 5, k2 = t & 31;
                *reinterpret_cast<uint32_t*>(smc + OFF_BHI + n * EP2 + k2 * 4) = bh[n * 64 + ks * 32 + k2];
                *reinterpret_cast<uint32_t*>(smc + OFF_BLO + n * EP2 + k2 * 4) = bl[n * 64 + ks * 32 + k2];
            }
        }
        __syncthreads();

#pragma unroll
        for (int kk = 0; kk < 4; kk++) {
            uint32_t aH[4], aL[4];
            uint32_t aaddr = aBase + kk * 32;
            ldsm_x4(aH, aaddr);
            ldsm_x4(aL, aaddr + (OFF_ALO - OFF_AHI));
#pragma unroll
            for (int ntp = 0; ntp < 4; ntp++) {
                uint32_t bH[4], bL[4];
                uint32_t baddr = smb + OFF_BHI + (colhalf + ntp * 16 + bRowSel) * EP2
                               + kk * 32 + bColSel;
                ldsm_x4(bH, baddr);
                ldsm_x4(bL, baddr + (OFF_BLO - OFF_BHI));
                mma_bf16(acc[2 * ntp],     aH, &bH[0]);
                mma_bf16(acc[2 * ntp],     aH, &bL[0]);
                mma_bf16(acc[2 * ntp],     aL, &bH[0]);
                mma_bf16(acc[2 * ntp + 1], aH, &bH[2]);
                mma_bf16(acc[2 * ntp + 1], aH, &bL[2]);
                mma_bf16(acc[2 * ntp + 1], aL, &bH[2]);
            }
        }
    }

    {
        int r0 = slab + (lid >> 2);
        int cb2 = (lid & 3) * 2;
        bool ok0 = (eb + r0 < NN), ok1 = (eb + r0 + 8 < NN);
        float* d0 = g_mid + (size_t)(eb + r0) * 256 + colsec * 128 + colhalf;
        float* d1 = g_mid + (size_t)(eb + r0 + 8) * 256 + colsec * 128 + colhalf;
        const float* bp = g_biasf + colsec * 128 + colhalf;
#pragma unroll
        for (int nt = 0; nt < 8; nt++) {
            int c = nt * 8 + cb2;
            float b0 = bp[c], b1 = bp[c + 1];
            if (ok0) *reinterpret_cast<float2*>(d0 + c) =
                make_float2(fmaxf(acc[nt][0] + b0, 0.f), fmaxf(acc[nt][1] + b1, 0.f));
            if (ok1) *reinterpret_cast<float2*>(d1 + c) =
                make_float2(fmaxf(acc[nt][2] + b0, 0.f), fmaxf(acc[nt][3] + b1, 0.f));
        }
    }
}

// ===== K5b: FFN GEMM2: x2 = BN_n1(x1) + mid @ Wf2 + bf2; n2-stats ==========
__global__ __launch_bounds__(512, 2) void k_ffn2(
    const float* __restrict__ gn1, const float* __restrict__ ben1)
{
    extern __shared__ char smc[];
    const uint32_t smb = smem_u32(smc);
    float* scs = reinterpret_cast<float*>(smc + SM_GEMM_TOTAL);
    float* shs = scs + 128;
    const int tid = threadIdx.x;
    const int wid = tid >> 5, lid = tid & 31;
    const int eb = blockIdx.x * 128;
    const int slab = (wid >> 1) * 16;
    const int colhalf = (wid & 1) * 64;

    if (tid < 128) {
        float m = g_stats[512 + tid] * (1.f / NN);
        float v = g_stats[640 + tid] * (1.f / NN) - m * m;
        float sc = gn1[tid] * rsqrtf(v + 1e-5f);
        scs[tid] = sc;
        shs[tid] = ben1[tid] - m * sc;
    }
    __syncthreads();

    float acc[8][4];
#pragma unroll
    for (int i = 0; i < 8; i++)
#pragma unroll
        for (int j = 0; j < 4; j++) acc[i][j] = 0.f;

    const uint32_t aBase = smb + OFF_AHI + (slab + (lid & 15)) * EP2 + (lid >> 4) * 16;
    const uint32_t bRowSel = (lid & 7) + ((lid >> 4) << 3);
    const uint32_t bColSel = ((lid >> 3) & 1) * 16;

#pragma unroll 1
    for (int ks = 0; ks < 4; ks++) {
        if (ks) __syncthreads();
        {
            const float4 z4 = make_float4(0.f, 0.f, 0.f, 0.f);
            for (int t = tid; t < 2048; t += 512) {
                int r = t >> 4, c4 = t & 15, k0 = c4 * 4;
                float4 v = (eb + r < NN) ? ld4(g_mid + (size_t)(eb + r) * 256 + ks * 64 + k0) : z4;
                split_store(smc + OFF_AHI + r * EP2 + k0 * 2,
                            smc + OFF_ALO + r * EP2 + k0 * 2, v);
            }
        }
        {
            const uint32_t* bh = reinterpret_cast<const uint32_t*>(g_wf2t_hi);
            const uint32_t* bl = reinterpret_cast<const uint32_t*>(g_wf2t_lo);
            for (int t = tid; t < 4096; t += 512) {
                int n = t >> 5, k2 = t & 31;
                *reinterpret_cast<uint32_t*>(smc + OFF_BHI + n * EP2 + k2 * 4) = bh[n * 128 + ks * 32 + k2];
                *reinterpret_cast<uint32_t*>(smc + OFF_BLO + n * EP2 + k2 * 4) = bl[n * 128 + ks * 32 + k2];
            }
        }
        __syncthreads();

#pragma unroll
        for (int kk = 0; kk < 4; kk++) {
            uint32_t aH[4], aL[4];
            uint32_t aaddr = aBase + kk * 32;
            ldsm_x4(aH, aaddr);
            ldsm_x4(aL, aaddr + (OFF_ALO - OFF_AHI));
#pragma unroll
            for (int ntp = 0; ntp < 4; ntp++) {
                uint32_t bH[4], bL[4];
                uint32_t baddr = smb + OFF_BHI + (colhalf + ntp * 16 + bRowSel) * EP2
                               + kk * 32 + bColSel;
                ldsm_x4(bH, baddr);
                ldsm_x4(bL, baddr + (OFF_BLO - OFF_BHI));
                mma_bf16(acc[2 * ntp],     aH, &bH[0]);
                mma_bf16(acc[2 * ntp],     aH, &bL[0]);
                mma_bf16(acc[2 * ntp],     aL, &bH[0]);
                mma_bf16(acc[2 * ntp + 1], aH, &bH[2]);
                mma_bf16(acc[2 * ntp + 1], aH, &bL[2]);
                mma_bf16(acc[2 * ntp + 1], aL, &bH[2]);
            }
        }
    }
    __syncthreads();   // A/B regions now dead; reuse for stats

    float* sS = reinterpret_cast<float*>(smc + OFF_AHI);
    float* sQ = sS + 128;
    if (tid < 128) { sS[tid] = 0.f; sQ[tid] = 0.f; }
    __syncthreads();

    {
        int r0 = slab + (lid >> 2);
        int cb2 = (lid & 3) * 2;
        bool ok0 = (eb + r0 < NN), ok1 = (eb + r0 + 8 < NN);
#pragma unroll
        for (int nt = 0; nt < 8; nt++) {
            int c = colhalf + nt * 8 + cb2;
            float b0 = g_biasf[256 + c], b1 = g_biasf[256 + c + 1];
            float s0 = 0.f, q0 = 0.f, s1 = 0.f, q1 = 0.f;
            if (ok0) {
                int gr = eb + r0;
                float h0 = g_x1[(size_t)gr * 128 + c] * scs[c] + shs[c];
                float h1 = g_x1[(size_t)gr * 128 + c + 1] * scs[c + 1] + shs[c + 1];
                float o0 = h0 + acc[nt][0] + b0;
                float o1 = h1 + acc[nt][1] + b1;
                *reinterpret_cast<float2*>(g_x2 + (size_t)gr * 128 + c) = make_float2(o0, o1);
                s0 += o0; q0 += o0 * o0; s1 += o1; q1 += o1 * o1;
            }
            if (ok1) {
                int gr = eb + r0 + 8;
                float h0 = g_x1[(size_t)gr * 128 + c] * scs[c] + shs[c];
                float h1 = g_x1[(size_t)gr * 128 + c + 1] * scs[c + 1] + shs[c + 1];
                float o0 = h0 + acc[nt][2] + b0;
                float o1 = h1 + acc[nt][3] + b1;
                *reinterpret_cast<float2*>(g_x2 + (size_t)gr * 128 + c) = make_float2(o0, o1);
                s0 += o0; q0 += o0 * o0; s1 += o1; q1 += o1 * o1;
            }
            atomicAdd(&sS[c], s0);     atomicAdd(&sQ[c], q0);
            atomicAdd(&sS[c + 1], s1); atomicAdd(&sQ[c + 1], q1);
        }
    }
    __syncthreads();
    if (tid < 128) {
        atomicAdd(&g_stats[768 + tid], sS[tid]);
        atomicAdd(&g_stats[896 + tid], sQ[tid]);
    }
}

// ===== K6: x_out = BN_n2(x2) ================================================
__global__ void k_out_x(float* __restrict__ out,
                        const float* __restrict__ gn2, const float* __restrict__ ben2)
{
    int idx = blockIdx.x * blockDim.x + threadIdx.x;
    if (idx >= NN * 32) return;
    int c0 = (idx & 31) * 4;
    float4 v = reinterpret_cast<const float4*>(g_x2)[idx];
    float val[4] = { v.x, v.y, v.z, v.w };
    float o[4];
#pragma unroll
    for (int j = 0; j < 4; j++) {
        int c = c0 + j;
        float m = g_stats[768 + c] * (1.f / NN);
        float var = g_stats[896 + c] * (1.f / NN) - m * m;
        o[j] = gn2[c] * (val[j] - m) * rsqrtf(var + 1e-5f) + ben2[c];
    }
    reinterpret_cast<float4*>(out)[idx] = make_float4(o[0], o[1], o[2], o[3]);
}

// ===== K7: e_out = e + relu(BN_e(e_ij)) =====================================
__global__ void k_out_e(const float* __restrict__ e, float* __restrict__ out,
                        const float* __restrict__ ge, const float* __restrict__ bee)
{
    size_t idx = (size_t)blockIdx.x * blockDim.x + threadIdx.x;
    if (idx >= (size_t)NE * 32) return;
    int c0 = ((int)(idx & 31)) * 4;
    float4 v = reinterpret_cast<const float4*>(g_eij)[idx];
    float4 ev = reinterpret_cast<const float4*>(e)[idx];
    float val[4] = { v.x, v.y, v.z, v.w };
    float res[4] = { ev.x, ev.y, ev.z, ev.w };
    float o[4];
#pragma unroll
    for (int j = 0; j < 4; j++) {
        int c = c0 + j;
        float m = g_stats[c] * (1.f / NE);
        float var = g_stats[128 + c] * (1.f / NE) - m * m;
        float bn = ge[c] * (val[j] - m) * rsqrtf(var + 1e-5f) + bee[c];
        o[j] = res[j] + fmaxf(bn, 0.f);
    }
    reinterpret_cast<float4*>(out + (size_t)NN * DD)[idx] = make_float4(o[0], o[1], o[2], o[3]);
}

// ===== launch ===============================================================
extern "C" void kernel_launch(void* const* d_in, const int* in_sizes, int n_in,
                              void* d_out, int out_size)
{
    const float* x   = (const float*)d_in[0];
    const float* e   = (const float*)d_in[1];
    const int*   eidx= (const int*)  d_in[2];
    const float* WA  = (const float*)d_in[3];  const float* bA  = (const float*)d_in[4];
    const float* WB  = (const float*)d_in[5];  const float* bB  = (const float*)d_in[6];
    const float* WC  = (const float*)d_in[7];  const float* bC  = (const float*)d_in[8];
    const float* WD  = (const float*)d_in[9];  const float* bD  = (const float*)d_in[10];
    const float* WE  = (const float*)d_in[11]; const float* bE  = (const float*)d_in[12];
    const float* gx  = (const float*)d_in[13]; const float* bex = (const float*)d_in[14];
    const float* ge  = (const float*)d_in[15]; const float* bee = (const float*)d_in[16];
    const float* Wf1 = (const float*)d_in[17]; const float* bf1 = (const float*)d_in[18];
    const float* Wf2 = (const float*)d_in[19]; const float* bf2 = (const float*)d_in[20];
    const float* gn1 = (const float*)d_in[21]; const float* ben1= (const float*)d_in[22];
    const float* gn2 = (const float*)d_in[23]; const float* ben2= (const float*)d_in[24];
    float* out = (float*)d_out;

    static cudaStream_t s2 = nullptr;
    static cudaEvent_t evFork0 = nullptr, evZero = nullptr, evFork = nullptr, evJoin = nullptr;
    if (!s2) {
        cudaStreamCreateWithFlags(&s2, cudaStreamNonBlocking);
        cudaEventCreateWithFlags(&evFork0, cudaEventDisableTiming);
        cudaEventCreateWithFlags(&evZero,  cudaEventDisableTiming);
        cudaEventCreateWithFlags(&evFork,  cudaEventDisableTiming);
        cudaEventCreateWithFlags(&evJoin,  cudaEventDisableTiming);
    }

    void *p_num, *p_den, *p_st;
    cudaGetSymbolAddress(&p_num, g_num);
    cudaGetSymbolAddress(&p_den, g_den);
    cudaGetSymbolAddress(&p_st,  g_stats);

    cudaFuncSetAttribute(k_node_gemm_mma, cudaFuncAttributeMaxDynamicSharedMemorySize, SM_GEMM_TOTAL);
    cudaFuncSetAttribute(k_edge_fused,    cudaFuncAttributeMaxDynamicSharedMemorySize, SM_GEMM_TOTAL);
    cudaFuncSetAttribute(k_ffn1,          cudaFuncAttributeMaxDynamicSharedMemorySize, SM_FFN_TOTAL);
    cudaFuncSetAttribute(k_ffn2,          cudaFuncAttributeMaxDynamicSharedMemorySize, SM_FFN_TOTAL);

    // fork s2: memsets run concurrently with prep + node GEMM
    cudaEventRecord(evFork0, 0);
    cudaStreamWaitEvent(s2, evFork0, 0);
    cudaMemsetAsync(p_num, 0, sizeof(float) * NN * DD, s2);
    cudaMemsetAsync(p_den, 0, sizeof(float) * NN * DD, s2);
    cudaMemsetAsync(p_st,  0, sizeof(float) * 8 * DD, s2);
    cudaEventRecord(evZero, s2);

    k_prep_w4<<<256, 256>>>(WA, WB, WD, WE, bA, bB, bD, bE);
    k_node_gemm_mma<<<dim3(NBLK_N, 4), 512, SM_GEMM_TOTAL>>>(x);
    k_prep_wct<<<64, 256>>>(WC);

    // join: edge_fused needs zeroed num/den/stats
    cudaStreamWaitEvent(0, evZero, 0);
    k_edge_fused<<<NBLK_E, 512, SM_GEMM_TOTAL>>>(e, eidx, bC);

    // fork: e_out path runs concurrently with the node chain
    cudaEventRecord(evFork, 0);
    cudaStreamWaitEvent(s2, evFork, 0);
    k_out_e<<<(int)(((size_t)NE * 32 + 255) / 256), 256, 0, s2>>>(e, out, ge, bee);
    cudaEventRecord(evJoin, s2);

    k_node_t2<<<(NN + 63) / 64, 256>>>();
    k_node_x12<<<(NN + 63) / 64, 256>>>(x, gx, bex);
    k_prep_wf<<<256, 256>>>(Wf1, Wf2, bf1, bf2);
    k_ffn1<<<dim3(NBLK_N, 2), 512, SM_FFN_TOTAL>>>(gn1, ben1);
    k_ffn2<<<NBLK_N, 512, SM_FFN_TOTAL>>>(gn1, ben1);
    k_out_x<<<(NN * 32 + 255) / 256, 256>>>(out, gn2, ben2);

    // join: main stream completes only after e_out is done
    cudaStreamWaitEvent(0, evJoin, 0);
}

// round 17
// speedup vs baseline: 1.0408x; 1.0039x over previous
#include <cuda_runtime.h>
#include <cuda_bf16.h>
#include <math.h>
#include <stdint.h>

#define NN 50000
#define NE 600000
#define DD 128
#define NBLK_E ((NE + 127) / 128)   // 4688
#define NBLK_N ((NN + 127) / 128)   // 391

// ---------------- device scratch ----------------
__device__ __align__(16) float g_nodeABDE[NN * 512];   // [Ax|Bx|Dx|Ex]
__device__ __align__(16) float g_eij[(size_t)NE * DD];
__device__ __align__(16) float g_num[NN * DD];
__device__ __align__(16) float g_den[NN * DD];
__device__ __align__(16) float g_t[NN * DD];
__device__ __align__(16) float g_x1[NN * DD];
__device__ __align__(16) float g_x2[NN * DD];
__device__ __align__(16) float g_mid[NN * 256];
// [0]=e_sum [128]=e_sq [256]=x_sum [384]=x_sq [512]=n1_sum [640]=n1_sq [768]=n2_sum [896]=n2_sq
__device__ float g_stats[8 * DD];
// pre-split weights (transposed, [n][k] bf16 hi/lo)
__device__ __align__(16) __nv_bfloat16 g_wct_hi[128 * 128];
__device__ __align__(16) __nv_bfloat16 g_wct_lo[128 * 128];
__device__ __align__(16) __nv_bfloat16 g_w4t_hi[4 * 128 * 128];
__device__ __align__(16) __nv_bfloat16 g_w4t_lo[4 * 128 * 128];
__device__ __align__(16) __nv_bfloat16 g_wf1t_hi[256 * 128];
__device__ __align__(16) __nv_bfloat16 g_wf1t_lo[256 * 128];
__device__ __align__(16) __nv_bfloat16 g_wf2t_hi[128 * 256];
__device__ __align__(16) __nv_bfloat16 g_wf2t_lo[128 * 256];
__device__ float g_bias4[512];
__device__ float g_biasf[384];   // [0:256)=bf1, [256:384)=bf2

static __device__ __forceinline__ float4 ld4(const float* p) {
    return *reinterpret_cast<const float4*>(p);
}
static __device__ __forceinline__ void st4(float* p, float4 v) {
    *reinterpret_cast<float4*>(p) = v;
}
static __device__ __forceinline__ uint32_t smem_u32(const void* p) {
    uint32_t a;
    asm("{ .reg .u64 t; cvta.to.shared.u64 t, %1; cvt.u32.u64 %0, t; }" : "=r"(a) : "l"(p));
    return a;
}
static __device__ __forceinline__ void ldsm_x4(uint32_t* r, uint32_t addr) {
    asm volatile("ldmatrix.sync.aligned.m8n8.x4.shared.b16 {%0,%1,%2,%3}, [%4];"
                 : "=r"(r[0]), "=r"(r[1]), "=r"(r[2]), "=r"(r[3]) : "r"(addr));
}
static __device__ __forceinline__ void mma_bf16(float* d, const uint32_t* a, const uint32_t* b) {
    asm volatile("mma.sync.aligned.m16n8k16.row.col.f32.bf16.bf16.f32 "
                 "{%0,%1,%2,%3}, {%4,%5,%6,%7}, {%8,%9}, {%0,%1,%2,%3};"
                 : "+f"(d[0]), "+f"(d[1]), "+f"(d[2]), "+f"(d[3])
                 : "r"(a[0]), "r"(a[1]), "r"(a[2]), "r"(a[3]), "r"(b[0]), "r"(b[1]));
}
static __device__ __forceinline__ void split_store(char* hi, char* lo, float4 v) {
    __nv_bfloat16 h0 = __float2bfloat16(v.x);
    __nv_bfloat16 h1 = __float2bfloat16(v.y);
    __nv_bfloat16 h2 = __float2bfloat16(v.z);
    __nv_bfloat16 h3 = __float2bfloat16(v.w);
    __nv_bfloat16 l0 = __float2bfloat16(v.x - __bfloat162float(h0));
    __nv_bfloat16 l1 = __float2bfloat16(v.y - __bfloat162float(h1));
    __nv_bfloat16 l2 = __float2bfloat16(v.z - __bfloat162float(h2));
    __nv_bfloat16 l3 = __float2bfloat16(v.w - __bfloat162float(h3));
    *reinterpret_cast<__nv_bfloat162*>(hi)     = __nv_bfloat162(h0, h1);
    *reinterpret_cast<__nv_bfloat162*>(hi + 4) = __nv_bfloat162(h2, h3);
    *reinterpret_cast<__nv_bfloat162*>(lo)     = __nv_bfloat162(l0, l1);
    *reinterpret_cast<__nv_bfloat162*>(lo + 4) = __nv_bfloat162(l2, l3);
}

// smem layout for gemm kernels: K-split halves, 64 bf16 cols + 8 pad = 144B pitch
#define EP2      144
#define OFF_AHI  0
#define OFF_ALO  18432
#define OFF_BHI  36864
#define OFF_BLO  55296
#define SM_GEMM_TOTAL 73728
#define SM_FFN_TOTAL  74752   // + scs/shs (2*128 f32)

// ===== K0a: WC -> WC^T bf16 hi/lo ==========================================
__global__ void k_prep_wct(const float* __restrict__ WC)
{
    int idx = blockIdx.x * 256 + threadIdx.x;     // 16384
    int n = idx >> 7, k = idx & 127;
    float w = WC[k * 128 + n];
    __nv_bfloat16 h = __float2bfloat16(w);
    g_wct_hi[n * 128 + k] = h;
    g_wct_lo[n * 128 + k] = __float2bfloat16(w - __bfloat162float(h));
}

// ===== K0b: [WA|WB|WD|WE]^T -> bf16 hi/lo + bias pack ======================
__global__ void k_prep_w4(
    const float* __restrict__ WA, const float* __restrict__ WB,
    const float* __restrict__ WD, const float* __restrict__ WE,
    const float* __restrict__ bA, const float* __restrict__ bB,
    const float* __restrict__ bD, const float* __restrict__ bE)
{
    int idx = blockIdx.x * 256 + threadIdx.x;     // 65536
    int mat = idx >> 14, rem = idx & 16383;
    int n = rem >> 7, k = rem & 127;
    const float* W = (mat == 0) ? WA : (mat == 1) ? WB : (mat == 2) ? WD : WE;
    float w = W[k * 128 + n];
    __nv_bfloat16 h = __float2bfloat16(w);
    g_w4t_hi[idx] = h;
    g_w4t_lo[idx] = __float2bfloat16(w - __bfloat162float(h));
    if (k == 0) {
        const float* b = (mat == 0) ? bA : (mat == 1) ? bB : (mat == 2) ? bD : bE;
        g_bias4[mat * 128 + n] = b[n];
    }
}

// ===== K0c: Wf1^T, Wf2^T -> bf16 hi/lo + bias pack =========================
__global__ void k_prep_wf(
    const float* __restrict__ Wf1, const float* __restrict__ Wf2,
    const float* __restrict__ bf1, const float* __restrict__ bf2)
{
    int idx = blockIdx.x * 256 + threadIdx.x;     // 65536
    if (idx < 32768) {
        int n = idx >> 7, k = idx & 127;
        float w = Wf1[k * 256 + n];
        __nv_bfloat16 h = __float2bfloat16(w);
        g_wf1t_hi[n * 128 + k] = h;
        g_wf1t_lo[n * 128 + k] = __float2bfloat16(w - __bfloat162float(h));
        if (k == 0) g_biasf[n] = bf1[n];
    } else {
        int rem = idx - 32768;
        int n = rem >> 8, k = rem & 255;
        float w = Wf2[k * 128 + n];
        __nv_bfloat16 h = __float2bfloat16(w);
        g_wf2t_hi[n * 256 + k] = h;
        g_wf2t_lo[n * 256 + k] = __float2bfloat16(w - __bfloat162float(h));
        if (k == 0) g_biasf[256 + n] = bf2[n];
    }
}

// ===== K1: node 4-GEMM via mma.sync bf16 split =============================
__global__ __launch_bounds__(512, 2) void k_node_gemm_mma(const float* __restrict__ x)
{
    extern __shared__ char smc[];
    const uint32_t smb = smem_u32(smc);
    const int tid = threadIdx.x;
    const int wid = tid >> 5, lid = tid & 31;
    const int eb = blockIdx.x * 128;
    const int mat = blockIdx.y;
    const int slab = (wid >> 1) * 16;
    const int colhalf = (wid & 1) * 64;

    float acc[8][4];
#pragma unroll
    for (int i = 0; i < 8; i++)
#pragma unroll
        for (int j = 0; j < 4; j++) acc[i][j] = 0.f;

    const uint32_t aBase = smb + OFF_AHI + (slab + (lid & 15)) * EP2 + (lid >> 4) * 16;
    const uint32_t bRowSel = (lid & 7) + ((lid >> 4) << 3);
    const uint32_t bColSel = ((lid >> 3) & 1) * 16;

#pragma unroll 1
    for (int ks = 0; ks < 2; ks++) {
        if (ks) __syncthreads();
        {
            const float4 z4 = make_float4(0.f, 0.f, 0.f, 0.f);
            for (int t = tid; t < 2048; t += 512) {
                int r = t >> 4, c4 = t & 15, k0 = c4 * 4;
                float4 v = (eb + r < NN) ? ld4(x + (size_t)(eb + r) * 128 + ks * 64 + k0) : z4;
                split_store(smc + OFF_AHI + r * EP2 + k0 * 2,
                            smc + OFF_ALO + r * EP2 + k0 * 2, v);
            }
        }
        {
            const uint32_t* bh = reinterpret_cast<const uint32_t*>(g_w4t_hi) + mat * 8192;
            const uint32_t* bl = reinterpret_cast<const uint32_t*>(g_w4t_lo) + mat * 8192;
            for (int t = tid; t < 4096; t += 512) {
                int n = t >> 5, k2 = t & 31;
                *reinterpret_cast<uint32_t*>(smc + OFF_BHI + n * EP2 + k2 * 4) = bh[n * 64 + ks * 32 + k2];
                *reinterpret_cast<uint32_t*>(smc + OFF_BLO + n * EP2 + k2 * 4) = bl[n * 64 + ks * 32 + k2];
            }
        }
        __syncthreads();

#pragma unroll
        for (int kk = 0; kk < 4; kk++) {
            uint32_t aH[4], aL[4];
            uint32_t aaddr = aBase + kk * 32;
            ldsm_x4(aH, aaddr);
            ldsm_x4(aL, aaddr + (OFF_ALO - OFF_AHI));
#pragma unroll
            for (int ntp = 0; ntp < 4; ntp++) {
                uint32_t bH[4], bL[4];
                uint32_t baddr = smb + OFF_BHI + (colhalf + ntp * 16 + bRowSel) * EP2
                               + kk * 32 + bColSel;
                ldsm_x4(bH, baddr);
                ldsm_x4(bL, baddr + (OFF_BLO - OFF_BHI));
                mma_bf16(acc[2 * ntp],     aH, &bH[0]);
                mma_bf16(acc[2 * ntp],     aH, &bL[0]);
                mma_bf16(acc[2 * ntp],     aL, &bH[0]);
                mma_bf16(acc[2 * ntp + 1], aH, &bH[2]);
                mma_bf16(acc[2 * ntp + 1], aH, &bL[2]);
                mma_bf16(acc[2 * ntp + 1], aL, &bH[2]);
            }
        }
    }

    {
        int r0 = slab + (lid >> 2);
        int cb2 = (lid & 3) * 2;
        bool ok0 = (eb + r0 < NN), ok1 = (eb + r0 + 8 < NN);
        float* d0 = g_nodeABDE + (size_t)(eb + r0) * 512 + mat * 128 + colhalf;
        float* d1 = g_nodeABDE + (size_t)(eb + r0 + 8) * 512 + mat * 128 + colhalf;
        const float* bp = g_bias4 + mat * 128 + colhalf;
#pragma unroll
        for (int nt = 0; nt < 8; nt++) {
            int c = nt * 8 + cb2;
            float b0 = bp[c], b1 = bp[c + 1];
            if (ok0) *reinterpret_cast<float2*>(d0 + c) = make_float2(acc[nt][0] + b0, acc[nt][1] + b1);
            if (ok1) *reinterpret_cast<float2*>(d1 + c) = make_float2(acc[nt][2] + b0, acc[nt][3] + b1);
        }
    }
}

// ===== K2: FUSED edge GEMM + epilogue (scatter + sigma + e-stats) ==========
__global__ __launch_bounds__(512, 2) void k_edge_fused(
    const float* __restrict__ e, const int* __restrict__ eidx,
    const float* __restrict__ bC)
{
    extern __shared__ char smc[];
    const uint32_t smb = smem_u32(smc);
    const int tid = threadIdx.x;
    const int wid = tid >> 5, lid = tid & 31;
    const int eb = blockIdx.x * 128;
    const int slab = (wid >> 1) * 16;
    const int colhalf = (wid & 1) * 64;

    float acc[8][4];
#pragma unroll
    for (int i = 0; i < 8; i++)
#pragma unroll
        for (int j = 0; j < 4; j++) acc[i][j] = 0.f;

    const uint32_t aBase = smb + OFF_AHI + (slab + (lid & 15)) * EP2 + (lid >> 4) * 16;
    const uint32_t bRowSel = (lid & 7) + ((lid >> 4) << 3);
    const uint32_t bColSel = ((lid >> 3) & 1) * 16;

#pragma unroll 1
    for (int ks = 0; ks < 2; ks++) {
        if (ks) __syncthreads();
        {
            const float4 z4 = make_float4(0.f, 0.f, 0.f, 0.f);
            for (int t = tid; t < 2048; t += 512) {
                int r = t >> 4, c4 = t & 15, k0 = c4 * 4;
                float4 v = (eb + r < NE) ? ld4(e + (size_t)(eb + r) * 128 + ks * 64 + k0) : z4;
                split_store(smc + OFF_AHI + r * EP2 + k0 * 2,
                            smc + OFF_ALO + r * EP2 + k0 * 2, v);
            }
        }
        {
            const uint32_t* bh = reinterpret_cast<const uint32_t*>(g_wct_hi);
            const uint32_t* bl = reinterpret_cast<const uint32_t*>(g_wct_lo);
            for (int t = tid; t < 4096; t += 512) {
                int n = t >> 5, k2 = t & 31;
                *reinterpret_cast<uint32_t*>(smc + OFF_BHI + n * EP2 + k2 * 4) = bh[n * 64 + ks * 32 + k2];
                *reinterpret_cast<uint32_t*>(smc + OFF_BLO + n * EP2 + k2 * 4) = bl[n * 64 + ks * 32 + k2];
            }
        }
        __syncthreads();

#pragma unroll
        for (int kk = 0; kk < 4; kk++) {
            uint32_t aH[4], aL[4];
            uint32_t aaddr = aBase + kk * 32;
            ldsm_x4(aH, aaddr);
            ldsm_x4(aL, aaddr + (OFF_ALO - OFF_AHI));
#pragma unroll
            for (int ntp = 0; ntp < 4; ntp++) {
                uint32_t bH[4], bL[4];
                uint32_t baddr = smb + OFF_BHI + (colhalf + ntp * 16 + bRowSel) * EP2
                               + kk * 32 + bColSel;
                ldsm_x4(bH, baddr);
                ldsm_x4(bL, baddr + (OFF_BLO - OFF_BHI));
                mma_bf16(acc[2 * ntp],     aH, &bH[0]);
                mma_bf16(acc[2 * ntp],     aH, &bL[0]);
                mma_bf16(acc[2 * ntp],     aL, &bH[0]);
                mma_bf16(acc[2 * ntp + 1], aH, &bH[2]);
                mma_bf16(acc[2 * ntp + 1], aH, &bL[2]);
                mma_bf16(acc[2 * ntp + 1], aL, &bH[2]);
            }
        }
    }
    __syncthreads();   // mainloop done reading A/B smem

    // ---- stage Ce into smem (pitch 130 f32) ----
    float* Dsm = reinterpret_cast<float*>(smc);
    {
        int r0 = slab + (lid >> 2);
        int cb2 = (lid & 3) * 2;
#pragma unroll
        for (int nt = 0; nt < 8; nt++) {
            int c = colhalf + nt * 8 + cb2;
            *reinterpret_cast<float2*>(&Dsm[r0 * 130 + c])       = make_float2(acc[nt][0], acc[nt][1]);
            *reinterpret_cast<float2*>(&Dsm[(r0 + 8) * 130 + c]) = make_float2(acc[nt][2], acc[nt][3]);
        }
    }
    __syncthreads();

    // ---- epilogue ----
    const int tx = tid & 15, ty = tid >> 4;
    float4 bc0 = ld4(bC + tx * 4), bc1 = ld4(bC + 64 + tx * 4);
    float ssum[8], ssq[8];
#pragma unroll
    for (int j = 0; j < 8; j++) { ssum[j] = 0.f; ssq[j] = 0.f; }

    const float4* nb = reinterpret_cast<const float4*>(g_nodeABDE);
    float4* numb = reinterpret_cast<float4*>(g_num);
    float4* denb = reinterpret_cast<float4*>(g_den);
    float4* eijb = reinterpret_cast<float4*>(g_eij);

    // batch the index loads for all 4 edges (MLP)
    int srcs[4], dsts[4];
#pragma unroll
    for (int i = 0; i < 4; i++) {
        int eg = eb + ty * 4 + i;
        srcs[i] = (eg < NE) ? eidx[eg] : 0;
        dsts[i] = (eg < NE) ? eidx[NE + eg] : 0;
    }

#pragma unroll
    for (int i = 0; i < 4; i++) {
        int lr = ty * 4 + i;
        int eg = eb + lr;
        if (eg >= NE) continue;
        int src = srcs[i];
        int dst = dsts[i];
#pragma unroll
        for (int cc = 0; cc < 2; cc++) {
            int c4 = tx + cc * 16;
            int col = c4 * 4;
            float a0 = Dsm[lr * 130 + col + 0];
            float a1 = Dsm[lr * 130 + col + 1];
            float a2 = Dsm[lr * 130 + col + 2];
            float a3 = Dsm[lr * 130 + col + 3];
            float4 dx = nb[(size_t)dst * 128 + 64 + c4];
            float4 ex = nb[(size_t)src * 128 + 96 + c4];
            float4 bx = nb[(size_t)src * 128 + 32 + c4];
            float4 bc = cc ? bc1 : bc0;
            float4 eij;
            eij.x = a0 + bc.x + dx.x + ex.x;
            eij.y = a1 + bc.y + dx.y + ex.y;
            eij.z = a2 + bc.z + dx.z + ex.z;
            eij.w = a3 + bc.w + dx.w + ex.w;
            eijb[(size_t)eg * 32 + c4] = eij;
            float4 sg;
            sg.x = 1.f / (1.f + __expf(-eij.x));
            sg.y = 1.f / (1.f + __expf(-eij.y));
            sg.z = 1.f / (1.f + __expf(-eij.z));
            sg.w = 1.f / (1.f + __expf(-eij.w));
            atomicAdd(numb + (size_t)dst * 32 + c4,
                      make_float4(sg.x * bx.x, sg.y * bx.y, sg.z * bx.z, sg.w * bx.w));
            atomicAdd(denb + (size_t)dst * 32 + c4, sg);
            ssum[cc * 4 + 0] += eij.x; ssq[cc * 4 + 0] += eij.x * eij.x;
            ssum[cc * 4 + 1] += eij.y; ssq[cc * 4 + 1] += eij.y * eij.y;
            ssum[cc * 4 + 2] += eij.z; ssq[cc * 4 + 2] += eij.z * eij.z;
            ssum[cc * 4 + 3] += eij.w; ssq[cc * 4 + 3] += eij.w * eij.w;
        }
    }
    __syncthreads();   // Dsm dead; reuse for stats reduce

    float* redS = reinterpret_cast<float*>(smc);            // 32 x 128
    float* redQ = reinterpret_cast<float*>(smc) + 4096;     // 32 x 128
#pragma unroll
    for (int cc = 0; cc < 2; cc++)
#pragma unroll
        for (int j = 0; j < 4; j++) {
            redS[ty * 128 + cc * 64 + tx * 4 + j] = ssum[cc * 4 + j];
            redQ[ty * 128 + cc * 64 + tx * 4 + j] = ssq[cc * 4 + j];
        }
    __syncthreads();
    if (tid < 128) {
        float s = 0.f, q = 0.f;
#pragma unroll
        for (int t = 0; t < 32; t++) { s += redS[t * 128 + tid]; q += redQ[t * 128 + tid]; }
        atomicAdd(&g_stats[tid], s);
        atomicAdd(&g_stats[128 + tid], q);
    }
}

// ===== K3: t = Ax + num/(den+eps); x-stats =================================
__global__ __launch_bounds__(256) void k_node_t2()
{
    __shared__ float sS[8 * 128], sQ[8 * 128];
    const int tid = threadIdx.x;
    const int c4 = tid & 31, g = tid >> 5;
    const int rb = blockIdx.x * 64;
    float s[4] = {0, 0, 0, 0}, q[4] = {0, 0, 0, 0};
#pragma unroll
    for (int p = 0; p < 8; p++) {
        int r = rb + p * 8 + g;
        if (r < NN) {
            float4 ax = ld4(g_nodeABDE + (size_t)r * 512 + c4 * 4);
            float4 nu = ld4(g_num + (size_t)r * 128 + c4 * 4);
            float4 de = ld4(g_den + (size_t)r * 128 + c4 * 4);
            float4 t;
            t.x = ax.x + nu.x / (de.x + 1e-6f);
            t.y = ax.y + nu.y / (de.y + 1e-6f);
            t.z = ax.z + nu.z / (de.z + 1e-6f);
            t.w = ax.w + nu.w / (de.w + 1e-6f);
            st4(g_t + (size_t)r * 128 + c4 * 4, t);
            s[0] += t.x; q[0] += t.x * t.x;
            s[1] += t.y; q[1] += t.y * t.y;
            s[2] += t.z; q[2] += t.z * t.z;
            s[3] += t.w; q[3] += t.w * t.w;
        }
    }
#pragma unroll
    for (int j = 0; j < 4; j++) { sS[g * 128 + c4 * 4 + j] = s[j]; sQ[g * 128 + c4 * 4 + j] = q[j]; }
    __syncthreads();
    if (tid < 128) {
        float a = 0.f, b = 0.f;
#pragma unroll
        for (int t = 0; t < 8; t++) { a += sS[t * 128 + tid]; b += sQ[t * 128 + tid]; }
        atomicAdd(&g_stats[256 + tid], a);
        atomicAdd(&g_stats[384 + tid], b);
    }
}

// ===== K4: x1 = x + relu(BN_x(t)); n1-stats ================================
__global__ __launch_bounds__(256) void k_node_x12(
    const float* __restrict__ x,
    const float* __restrict__ gx, const float* __restrict__ bex)
{
    __shared__ float sS[8 * 128], sQ[8 * 128];
    const int tid = threadIdx.x;
    const int c4 = tid & 31, g = tid >> 5;
    const int rb = blockIdx.x * 64;
    float sc[4], sh[4];
#pragma unroll
    for (int j = 0; j < 4; j++) {
        int c = c4 * 4 + j;
        float m = g_stats[256 + c] * (1.f / NN);
        float v = g_stats[384 + c] * (1.f / NN) - m * m;
        sc[j] = gx[c] * rsqrtf(v + 1e-5f);
        sh[j] = bex[c] - m * sc[j];
    }
    float s[4] = {0, 0, 0, 0}, q[4] = {0, 0, 0, 0};
#pragma unroll
    for (int p = 0; p < 8; p++) {
        int r = rb + p * 8 + g;
        if (r < NN) {
            float4 t = ld4(g_t + (size_t)r * 128 + c4 * 4);
            float4 xv = ld4(x + (size_t)r * 128 + c4 * 4);
            float4 o;
            o.x = xv.x + fmaxf(t.x * sc[0] + sh[0], 0.f);
            o.y = xv.y + fmaxf(t.y * sc[1] + sh[1], 0.f);
            o.z = xv.z + fmaxf(t.z * sc[2] + sh[2], 0.f);
            o.w = xv.w + fmaxf(t.w * sc[3] + sh[3], 0.f);
            st4(g_x1 + (size_t)r * 128 + c4 * 4, o);
            s[0] += o.x; q[0] += o.x * o.x;
            s[1] += o.y; q[1] += o.y * o.y;
            s[2] += o.z; q[2] += o.z * o.z;
            s[3] += o.w; q[3] += o.w * o.w;
        }
    }
#pragma unroll
    for (int j = 0; j < 4; j++) { sS[g * 128 + c4 * 4 + j] = s[j]; sQ[g * 128 + c4 * 4 + j] = q[j]; }
    __syncthreads();
    if (tid < 128) {
        float a = 0.f, b = 0.f;
#pragma unroll
        for (int t = 0; t < 8; t++) { a += sS[t * 128 + tid]; b += sQ[t * 128 + tid]; }
        atomicAdd(&g_stats[512 + tid], a);
        atomicAdd(&g_stats[640 + tid], b);
    }
}

// ===== K5a: FFN GEMM1: mid = relu(BN_n1(x1) @ Wf1 + bf1) ===================
__global__ __launch_bounds__(512, 2) void k_ffn1(
    const float* __restrict__ gn1, const float* __restrict__ ben1)
{
    extern __shared__ char smc[];
    const uint32_t smb = smem_u32(smc);
    float* scs = reinterpret_cast<float*>(smc + SM_GEMM_TOTAL);
    float* shs = scs + 128;
    const int tid = threadIdx.x;
    const int wid = tid >> 5, lid = tid & 31;
    const int eb = blockIdx.x * 128;
    const int colsec = blockIdx.y;
    const int slab = (wid >> 1) * 16;
    const int colhalf = (wid & 1) * 64;

    if (tid < 128) {
        float m = g_stats[512 + tid] * (1.f / NN);
        float v = g_stats[640 + tid] * (1.f / NN) - m * m;
        float sc = gn1[tid] * rsqrtf(v + 1e-5f);
        scs[tid] = sc;
        shs[tid] = ben1[tid] - m * sc;
    }
    __syncthreads();

    float acc[8][4];
#pragma unroll
    for (int i = 0; i < 8; i++)
#pragma unroll
        for (int j = 0; j < 4; j++) acc[i][j] = 0.f;

    const uint32_t aBase = smb + OFF_AHI + (slab + (lid & 15)) * EP2 + (lid >> 4) * 16;
    const uint32_t bRowSel = (lid & 7) + ((lid >> 4) << 3);
    const uint32_t bColSel = ((lid >> 3) & 1) * 16;

#pragma unroll 1
    for (int ks = 0; ks < 2; ks++) {
        if (ks) __syncthreads();
        {
            const float4 z4 = make_float4(0.f, 0.f, 0.f, 0.f);
            for (int t = tid; t < 2048; t += 512) {
                int r = t >> 4, c4 = t & 15, k0 = c4 * 4;
                int col = ks * 64 + k0;
                float4 v = (eb + r < NN) ? ld4(g_x1 + (size_t)(eb + r) * 128 + col) : z4;
                float4 h;
                h.x = v.x * scs[col + 0] + shs[col + 0];
                h.y = v.y * scs[col + 1] + shs[col + 1];
                h.z = v.z * scs[col + 2] + shs[col + 2];
                h.w = v.w * scs[col + 3] + shs[col + 3];
                split_store(smc + OFF_AHI + r * EP2 + k0 * 2,
                            smc + OFF_ALO + r * EP2 + k0 * 2, h);
            }
        }
        {
            const uint32_t* bh = reinterpret_cast<const uint32_t*>(g_wf1t_hi) + colsec * 8192;
            const uint32_t* bl = reinterpret_cast<const uint32_t*>(g_wf1t_lo) + colsec * 8192;
            for (int t = tid; t < 4096; t += 512) {
                int n = t >> 5, k2 = t & 31;
                *reinterpret_cast<uint32_t*>(smc + OFF_BHI + n * EP2 + k2 * 4) = bh[n * 64 + ks * 32 + k2];
                *reinterpret_cast<uint32_t*>(smc + OFF_BLO + n * EP2 + k2 * 4) = bl[n * 64 + ks * 32 + k2];
            }
        }
        __syncthreads();

#pragma unroll
        for (int kk = 0; kk < 4; kk++) {
            uint32_t aH[4], aL[4];
            uint32_t aaddr = aBase + kk * 32;
            ldsm_x4(aH, aaddr);
            ldsm_x4(aL, aaddr + (OFF_ALO - OFF_AHI));
#pragma unroll
            for (int ntp = 0; ntp < 4; ntp++) {
                uint32_t bH[4], bL[4];
                uint32_t baddr = smb + OFF_BHI + (colhalf + ntp * 16 + bRowSel) * EP2
                               + kk * 32 + bColSel;
                ldsm_x4(bH, baddr);
                ldsm_x4(bL, baddr + (OFF_BLO - OFF_BHI));
                mma_bf16(acc[2 * ntp],     aH, &bH[0]);
                mma_bf16(acc[2 * ntp],     aH, &bL[0]);
                mma_bf16(acc[2 * ntp],     aL, &bH[0]);
                mma_bf16(acc[2 * ntp + 1], aH, &bH[2]);
                mma_bf16(acc[2 * ntp + 1], aH, &bL[2]);
                mma_bf16(acc[2 * ntp + 1], aL, &bH[2]);
            }
        }
    }

    {
        int r0 = slab + (lid >> 2);
        int cb2 = (lid & 3) * 2;
        bool ok0 = (eb + r0 < NN), ok1 = (eb + r0 + 8 < NN);
        float* d0 = g_mid + (size_t)(eb + r0) * 256 + colsec * 128 + colhalf;
        float* d1 = g_mid + (size_t)(eb + r0 + 8) * 256 + colsec * 128 + colhalf;
        const float* bp = g_biasf + colsec * 128 + colhalf;
#pragma unroll
        for (int nt = 0; nt < 8; nt++) {
            int c = nt * 8 + cb2;
            float b0 = bp[c], b1 = bp[c + 1];
            if (ok0) *reinterpret_cast<float2*>(d0 + c) =
                make_float2(fmaxf(acc[nt][0] + b0, 0.f), fmaxf(acc[nt][1] + b1, 0.f));
            if (ok1) *reinterpret_cast<float2*>(d1 + c) =
                make_float2(fmaxf(acc[nt][2] + b0, 0.f), fmaxf(acc[nt][3] + b1, 0.f));
        }
    }
}

// ===== K5b: FFN GEMM2: x2 = BN_n1(x1) + mid @ Wf2 + bf2; n2-stats ==========
__global__ __launch_bounds__(512, 2) void k_ffn2(
    const float* __restrict__ gn1, const float* __restrict__ ben1)
{
    extern __shared__ char smc[];
    const uint32_t smb = smem_u32(smc);
    float* scs = reinterpret_cast<float*>(smc + SM_GEMM_TOTAL);
    float* shs = scs + 128;
    const int tid = threadIdx.x;
    const int wid = tid >> 5, lid = tid & 31;
    const int eb = blockIdx.x * 128;
    const int slab = (wid >> 1) * 16;
    const int colhalf = (wid & 1) * 64;

    if (tid < 128) {
        float m = g_stats[512 + tid] * (1.f / NN);
        float v = g_stats[640 + tid] * (1.f / NN) - m * m;
        float sc = gn1[tid] * rsqrtf(v + 1e-5f);
        scs[tid] = sc;
        shs[tid] = ben1[tid] - m * sc;
    }
    __syncthreads();

    float acc[8][4];
#pragma unroll
    for (int i = 0; i < 8; i++)
#pragma unroll
        for (int j = 0; j < 4; j++) acc[i][j] = 0.f;

    const uint32_t aBase = smb + OFF_AHI + (slab + (lid & 15)) * EP2 + (lid >> 4) * 16;
    const uint32_t bRowSel = (lid & 7) + ((lid >> 4) << 3);
    const uint32_t bColSel = ((lid >> 3) & 1) * 16;

#pragma unroll 1
    for (int ks = 0; ks < 4; ks++) {
        if (ks) __syncthreads();
        {
            const float4 z4 = make_float4(0.f, 0.f, 0.f, 0.f);
            for (int t = tid; t < 2048; t += 512) {
                int r = t >> 4, c4 = t & 15, k0 = c4 * 4;
                float4 v = (eb + r < NN) ? ld4(g_mid + (size_t)(eb + r) * 256 + ks * 64 + k0) : z4;
                split_store(smc + OFF_AHI + r * EP2 + k0 * 2,
                            smc + OFF_ALO + r * EP2 + k0 * 2, v);
            }
        }
        {
            const uint32_t* bh = reinterpret_cast<const uint32_t*>(g_wf2t_hi);
            const uint32_t* bl = reinterpret_cast<const uint32_t*>(g_wf2t_lo);
            for (int t = tid; t < 4096; t += 512) {
                int n = t >> 5, k2 = t & 31;
                *reinterpret_cast<uint32_t*>(smc + OFF_BHI + n * EP2 + k2 * 4) = bh[n * 128 + ks * 32 + k2];
                *reinterpret_cast<uint32_t*>(smc + OFF_BLO + n * EP2 + k2 * 4) = bl[n * 128 + ks * 32 + k2];
            }
        }
        __syncthreads();

#pragma unroll
        for (int kk = 0; kk < 4; kk++) {
            uint32_t aH[4], aL[4];
            uint32_t aaddr = aBase + kk * 32;
            ldsm_x4(aH, aaddr);
            ldsm_x4(aL, aaddr + (OFF_ALO - OFF_AHI));
#pragma unroll
            for (int ntp = 0; ntp < 4; ntp++) {
                uint32_t bH[4], bL[4];
                uint32_t baddr = smb + OFF_BHI + (colhalf + ntp * 16 + bRowSel) * EP2
                               + kk * 32 + bColSel;
                ldsm_x4(bH, baddr);
                ldsm_x4(bL, baddr + (OFF_BLO - OFF_BHI));
                mma_bf16(acc[2 * ntp],     aH, &bH[0]);
                mma_bf16(acc[2 * ntp],     aH, &bL[0]);
                mma_bf16(acc[2 * ntp],     aL, &bH[0]);
                mma_bf16(acc[2 * ntp + 1], aH, &bH[2]);
                mma_bf16(acc[2 * ntp + 1], aH, &bL[2]);
                mma_bf16(acc[2 * ntp + 1], aL, &bH[2]);
            }
        }
    }
    __syncthreads();   // A/B regions now dead; reuse for stats

    float* sS = reinterpret_cast<float*>(smc + OFF_AHI);
    float* sQ = sS + 128;
    if (tid < 128) { sS[tid] = 0.f; sQ[tid] = 0.f; }
    __syncthreads();

    {
        int r0 = slab + (lid >> 2);
        int cb2 = (lid & 3) * 2;
        bool ok0 = (eb + r0 < NN), ok1 = (eb + r0 + 8 < NN);
#pragma unroll
        for (int nt = 0; nt < 8; nt++) {
            int c = colhalf + nt * 8 + cb2;
            float b0 = g_biasf[256 + c], b1 = g_biasf[256 + c + 1];
            float s0 = 0.f, q0 = 0.f, s1 = 0.f, q1 = 0.f;
            if (ok0) {
                int gr = eb + r0;
                float h0 = g_x1[(size_t)gr * 128 + c] * scs[c] + shs[c];
                float h1 = g_x1[(size_t)gr * 128 + c + 1] * scs[c + 1] + shs[c + 1];
                float o0 = h0 + acc[nt][0] + b0;
                float o1 = h1 + acc[nt][1] + b1;
                *reinterpret_cast<float2*>(g_x2 + (size_t)gr * 128 + c) = make_float2(o0, o1);
                s0 += o0; q0 += o0 * o0; s1 += o1; q1 += o1 * o1;
            }
            if (ok1) {
                int gr = eb + r0 + 8;
                float h0 = g_x1[(size_t)gr * 128 + c] * scs[c] + shs[c];
                float h1 = g_x1[(size_t)gr * 128 + c + 1] * scs[c + 1] + shs[c + 1];
                float o0 = h0 + acc[nt][2] + b0;
                float o1 = h1 + acc[nt][3] + b1;
                *reinterpret_cast<float2*>(g_x2 + (size_t)gr * 128 + c) = make_float2(o0, o1);
                s0 += o0; q0 += o0 * o0; s1 += o1; q1 += o1 * o1;
            }
            atomicAdd(&sS[c], s0);     atomicAdd(&sQ[c], q0);
            atomicAdd(&sS[c + 1], s1); atomicAdd(&sQ[c + 1], q1);
        }
    }
    __syncthreads();
    if (tid < 128) {
        atomicAdd(&g_stats[768 + tid], sS[tid]);
        atomicAdd(&g_stats[896 + tid], sQ[tid]);
    }
}

// ===== K6: x_out = BN_n2(x2) ================================================
__global__ void k_out_x(float* __restrict__ out,
                        const float* __restrict__ gn2, const float* __restrict__ ben2)
{
    int idx = blockIdx.x * blockDim.x + threadIdx.x;
    if (idx >= NN * 32) return;
    int c0 = (idx & 31) * 4;
    float4 v = reinterpret_cast<const float4*>(g_x2)[idx];
    float val[4] = { v.x, v.y, v.z, v.w };
    float o[4];
#pragma unroll
    for (int j = 0; j < 4; j++) {
        int c = c0 + j;
        float m = g_stats[768 + c] * (1.f / NN);
        float var = g_stats[896 + c] * (1.f / NN) - m * m;
        o[j] = gn2[c] * (val[j] - m) * rsqrtf(var + 1e-5f) + ben2[c];
    }
    reinterpret_cast<float4*>(out)[idx] = make_float4(o[0], o[1], o[2], o[3]);
}

// ===== K7: e_out = e + relu(BN_e(e_ij)) =====================================
__global__ void k_out_e(const float* __restrict__ e, float* __restrict__ out,
                        const float* __restrict__ ge, const float* __restrict__ bee)
{
    size_t idx = (size_t)blockIdx.x * blockDim.x + threadIdx.x;
    if (idx >= (size_t)NE * 32) return;
    int c0 = ((int)(idx & 31)) * 4;
    float4 v = reinterpret_cast<const float4*>(g_eij)[idx];
    float4 ev = reinterpret_cast<const float4*>(e)[idx];
    float val[4] = { v.x, v.y, v.z, v.w };
    float res[4] = { ev.x, ev.y, ev.z, ev.w };
    float o[4];
#pragma unroll
    for (int j = 0; j < 4; j++) {
        int c = c0 + j;
        float m = g_stats[c] * (1.f / NE);
        float var = g_stats[128 + c] * (1.f / NE) - m * m;
        float bn = ge[c] * (val[j] - m) * rsqrtf(var + 1e-5f) + bee[c];
        o[j] = res[j] + fmaxf(bn, 0.f);
    }
    reinterpret_cast<float4*>(out + (size_t)NN * DD)[idx] = make_float4(o[0], o[1], o[2], o[3]);
}

// ===== launch ===============================================================
extern "C" void kernel_launch(void* const* d_in, const int* in_sizes, int n_in,
                              void* d_out, int out_size)
{
    const float* x   = (const float*)d_in[0];
    const float* e   = (const float*)d_in[1];
    const int*   eidx= (const int*)  d_in[2];
    const float* WA  = (const float*)d_in[3];  const float* bA  = (const float*)d_in[4];
    const float* WB  = (const float*)d_in[5];  const float* bB  = (const float*)d_in[6];
    const float* WC  = (const float*)d_in[7];  const float* bC  = (const float*)d_in[8];
    const float* WD  = (const float*)d_in[9];  const float* bD  = (const float*)d_in[10];
    const float* WE  = (const float*)d_in[11]; const float* bE  = (const float*)d_in[12];
    const float* gx  = (const float*)d_in[13]; const float* bex = (const float*)d_in[14];
    const float* ge  = (const float*)d_in[15]; const float* bee = (const float*)d_in[16];
    const float* Wf1 = (const float*)d_in[17]; const float* bf1 = (const float*)d_in[18];
    const float* Wf2 = (const float*)d_in[19]; const float* bf2 = (const float*)d_in[20];
    const float* gn1 = (const float*)d_in[21]; const float* ben1= (const float*)d_in[22];
    const float* gn2 = (const float*)d_in[23]; const float* ben2= (const float*)d_in[24];
    float* out = (float*)d_out;

    static cudaStream_t s2 = nullptr;
    static cudaEvent_t evFork0 = nullptr, evZero = nullptr, evFork = nullptr, evJoin = nullptr;
    if (!s2) {
        cudaStreamCreateWithFlags(&s2, cudaStreamNonBlocking);
        cudaEventCreateWithFlags(&evFork0, cudaEventDisableTiming);
        cudaEventCreateWithFlags(&evZero,  cudaEventDisableTiming);
        cudaEventCreateWithFlags(&evFork,  cudaEventDisableTiming);
        cudaEventCreateWithFlags(&evJoin,  cudaEventDisableTiming);
    }

    void *p_num, *p_den, *p_st;
    cudaGetSymbolAddress(&p_num, g_num);
    cudaGetSymbolAddress(&p_den, g_den);
    cudaGetSymbolAddress(&p_st,  g_stats);

    cudaFuncSetAttribute(k_node_gemm_mma, cudaFuncAttributeMaxDynamicSharedMemorySize, SM_GEMM_TOTAL);
    cudaFuncSetAttribute(k_edge_fused,    cudaFuncAttributeMaxDynamicSharedMemorySize, SM_GEMM_TOTAL);
    cudaFuncSetAttribute(k_ffn1,          cudaFuncAttributeMaxDynamicSharedMemorySize, SM_FFN_TOTAL);
    cudaFuncSetAttribute(k_ffn2,          cudaFuncAttributeMaxDynamicSharedMemorySize, SM_FFN_TOTAL);

    // fork s2: memsets + independent weight preps run under prep_w4 + node GEMM
    cudaEventRecord(evFork0, 0);
    cudaStreamWaitEvent(s2, evFork0, 0);
    cudaMemsetAsync(p_num, 0, sizeof(float) * NN * DD, s2);
    cudaMemsetAsync(p_den, 0, sizeof(float) * NN * DD, s2);
    cudaMemsetAsync(p_st,  0, sizeof(float) * 8 * DD, s2);
    k_prep_wct<<<64, 256, 0, s2>>>(WC);
    k_prep_wf<<<256, 256, 0, s2>>>(Wf1, Wf2, bf1, bf2);
    cudaEventRecord(evZero, s2);

    k_prep_w4<<<256, 256>>>(WA, WB, WD, WE, bA, bB, bD, bE);
    k_node_gemm_mma<<<dim3(NBLK_N, 4), 512, SM_GEMM_TOTAL>>>(x);

    // join: edge_fused needs zeroed num/den/stats + wct
    cudaStreamWaitEvent(0, evZero, 0);
    k_edge_fused<<<NBLK_E, 512, SM_GEMM_TOTAL>>>(e, eidx, bC);

    // fork: e_out path runs concurrently with the node chain
    cudaEventRecord(evFork, 0);
    cudaStreamWaitEvent(s2, evFork, 0);
    k_out_e<<<(int)(((size_t)NE * 32 + 255) / 256), 256, 0, s2>>>(e, out, ge, bee);
    cudaEventRecord(evJoin, s2);

    k_node_t2<<<(NN + 63) / 64, 256>>>();
    k_node_x12<<<(NN + 63) / 64, 256>>>(x, gx, bex);
    k_ffn1<<<dim3(NBLK_N, 2), 512, SM_FFN_TOTAL>>>(gn1, ben1);
    k_ffn2<<<NBLK_N, 512, SM_FFN_TOTAL>>>(gn1, ben1);
    k_out_x<<<(NN * 32 + 255) / 256, 256>>>(out, gn2, ben2);

    // join: main stream completes only after e_out is done
    cudaStreamWaitEvent(0, evJoin, 0);
}